// round 1
// baseline (speedup 1.0000x reference)
#include <cuda_runtime.h>
#include <math.h>

#define H        128
#define TILE_M   64
#define KC       32
#define SAS      (KC + 4)     // padded smem stride for A tile (conflict-free)
#define THREADS  256
#define MAX_N    50000
#define MAX_E    800000

// Scratch (device globals: no allocations allowed)
__device__ float g_agg[MAX_N * H];     // 25.6 MB   scatter-add target
__device__ float g_hid[MAX_E * H];     // 409.6 MB  edge hidden (reused as node hidden)
__device__ int   g_is64;

// ---------------------------------------------------------------------------
// edge_index dtype detection: jnp.int64 is silently int32 unless x64 enabled.
// int64 little-endian => words 1,3,5,7 are high words == 0 (indices < 50000).
// For int32 data those words are random indices; all-zero prob ~ (2e-5)^4.
// ---------------------------------------------------------------------------
__global__ void detect_idx_kernel(const unsigned int* __restrict__ e) {
    g_is64 = (e[1] == 0u && e[3] == 0u && e[5] == 0u && e[7] == 0u) ? 1 : 0;
}

__global__ void zero_agg_kernel(int n4) {
    int i = blockIdx.x * blockDim.x + threadIdx.x;
    if (i < n4) ((float4*)g_agg)[i] = make_float4(0.f, 0.f, 0.f, 0.f);
}

// ---- packed f32x2 helpers (sm_103a: FFMA2 doubles fp32 FMA throughput) ----
__device__ __forceinline__ unsigned long long pack2(float lo, float hi) {
    unsigned long long r;
    unsigned int a = __float_as_uint(lo), b = __float_as_uint(hi);
    asm("mov.b64 %0, {%1, %2};" : "=l"(r) : "r"(a), "r"(b));
    return r;
}
__device__ __forceinline__ void ffma2(unsigned long long& d,
                                      unsigned long long a,
                                      unsigned long long b) {
    asm("fma.rn.f32x2 %0, %1, %2, %0;" : "+l"(d) : "l"(a), "l"(b));
}
__device__ __forceinline__ float2 unpack2(unsigned long long v) {
    unsigned int lo, hi;
    asm("mov.b64 {%0, %1}, %2;" : "=r"(lo), "=r"(hi) : "l"(v));
    float2 f; f.x = __uint_as_float(lo); f.y = __uint_as_float(hi);
    return f;
}

// ---------------------------------------------------------------------------
// Persistent tall-skinny GEMM: C[M,128] = act(A[M,K] @ W[K,128] + b)
// MODE 0: edge L1. A = concat(x[row], x[col], edge_attr), ReLU, -> g_hid
// MODE 1: edge L2. A = g_hid, messages atomically scattered into g_agg[col]
// MODE 2: node L1. A = concat(x, g_agg), ReLU, -> g_hid (reuse)
// MODE 3: node L2. A = g_hid, -> Cout (d_out)
// Weights persistent in SMEM (loaded once per block, block persists over tiles).
// Each thread: 4 rows x 8 cols via 16 FFMA2 per k.
// ---------------------------------------------------------------------------
template<int K, int MODE>
__global__ void __launch_bounds__(THREADS)
gemm_kernel(const float* __restrict__ x,
            const float* __restrict__ eattr,
            const void*  __restrict__ eidx,
            const float* __restrict__ W,
            const float* __restrict__ bias,
            float* __restrict__ Cout,
            int M, int E)
{
    extern __shared__ __align__(16) float smem[];
    float* sW = smem;                       // K*128 floats
    float* sA = smem + K * H;               // TILE_M * SAS
    float* sB = sA + TILE_M * SAS;          // 128 floats
    __shared__ int sRow[TILE_M];
    __shared__ int sCol[TILE_M];

    const int tid = threadIdx.x;

    // Load weights + bias to SMEM once (block is persistent over tiles).
    for (int i = tid; i < K * H / 4; i += THREADS)
        ((float4*)sW)[i] = ((const float4*)W)[i];
    if (tid < H) sB[tid] = bias[tid];
    __syncthreads();

    const int ty = tid >> 4;        // 16 row-groups of 4 rows
    const int tx = tid & 15;        // 16 col-groups of 8 cols
    const int r0 = ty * 4;
    const int c0 = tx * 8;

    unsigned long long bpair[4];
    #pragma unroll
    for (int p = 0; p < 4; p++)
        bpair[p] = pack2(sB[c0 + 2 * p], sB[c0 + 2 * p + 1]);

    const int is64 = g_is64;
    const int ntiles = (M + TILE_M - 1) / TILE_M;

    for (int tile = blockIdx.x; tile < ntiles; tile += gridDim.x) {
        const int mbase = tile * TILE_M;
        const int mcount = min(TILE_M, M - mbase);

        __syncthreads();   // protect sRow/sCol + sA from previous tile
        if (MODE == 0 || MODE == 1) {
            if (tid < TILE_M) {
                int e = mbase + tid;
                int rI = 0, cI = 0;
                if (e < M) {
                    if (is64) {
                        const long long* p = (const long long*)eidx;
                        rI = (int)p[e];
                        cI = (int)p[(long long)E + e];
                    } else {
                        const int* p = (const int*)eidx;
                        rI = p[e];
                        cI = p[E + e];
                    }
                }
                sRow[tid] = rI;
                sCol[tid] = cI;
            }
        }
        __syncthreads();

        unsigned long long acc[4][4];
        #pragma unroll
        for (int r = 0; r < 4; r++)
            #pragma unroll
            for (int p = 0; p < 4; p++) acc[r][p] = bpair[p];

        for (int k0 = 0; k0 < K; k0 += KC) {
            // Stage A chunk [TILE_M x KC] into padded SMEM (float4 per thread x2)
            for (int f = tid; f < TILE_M * KC / 4; f += THREADS) {
                int r  = f >> 3;             // KC/4 = 8 float4 per row
                int kq = (f & 7) << 2;
                float4 v = make_float4(0.f, 0.f, 0.f, 0.f);
                if (r < mcount) {
                    int gk = k0 + kq;
                    const float* src;
                    if (MODE == 0) {
                        int seg = gk >> 7;
                        int lk  = gk & 127;
                        if (seg == 0)      src = x + (size_t)sRow[r] * H + lk;
                        else if (seg == 1) src = x + (size_t)sCol[r] * H + lk;
                        else               src = eattr + (size_t)(mbase + r) * H + lk;
                    } else if (MODE == 1 || MODE == 3) {
                        src = g_hid + (size_t)(mbase + r) * H + gk;
                    } else { // MODE 2: concat(x, agg)
                        if (gk < H) src = x + (size_t)(mbase + r) * H + gk;
                        else        src = g_agg + (size_t)(mbase + r) * H + (gk - H);
                    }
                    v = *(const float4*)src;
                }
                *(float4*)(&sA[r * SAS + kq]) = v;
            }
            __syncthreads();

            #pragma unroll
            for (int kk = 0; kk < KC; kk++) {
                unsigned long long ap[4];
                #pragma unroll
                for (int r = 0; r < 4; r++) {
                    float a = sA[(r0 + r) * SAS + kk];
                    ap[r] = pack2(a, a);
                }
                const float* wrow = &sW[(k0 + kk) * H + c0];
                ulonglong2 w01 = *(const ulonglong2*)(wrow);
                ulonglong2 w23 = *(const ulonglong2*)(wrow + 4);
                #pragma unroll
                for (int r = 0; r < 4; r++) {
                    ffma2(acc[r][0], ap[r], w01.x);
                    ffma2(acc[r][1], ap[r], w01.y);
                    ffma2(acc[r][2], ap[r], w23.x);
                    ffma2(acc[r][3], ap[r], w23.y);
                }
            }
            __syncthreads();
        }

        // Epilogue
        #pragma unroll
        for (int r = 0; r < 4; r++) {
            if (r0 + r >= mcount) continue;
            const int m = mbase + r0 + r;
            float vals[8];
            #pragma unroll
            for (int p = 0; p < 4; p++) {
                float2 f = unpack2(acc[r][p]);
                vals[2 * p]     = f.x;
                vals[2 * p + 1] = f.y;
            }
            if (MODE == 0 || MODE == 2) {
                #pragma unroll
                for (int i = 0; i < 8; i++) vals[i] = fmaxf(vals[i], 0.f);
                float4* dst = (float4*)(g_hid + (size_t)m * H + c0);
                dst[0] = make_float4(vals[0], vals[1], vals[2], vals[3]);
                dst[1] = make_float4(vals[4], vals[5], vals[6], vals[7]);
            } else if (MODE == 1) {
                const int node = sCol[r0 + r];
                float* dst = g_agg + (size_t)node * H + c0;
                #pragma unroll
                for (int i = 0; i < 8; i++) atomicAdd(dst + i, vals[i]);
            } else { // MODE 3
                float4* dst = (float4*)(Cout + (size_t)m * H + c0);
                dst[0] = make_float4(vals[0], vals[1], vals[2], vals[3]);
                dst[1] = make_float4(vals[4], vals[5], vals[6], vals[7]);
            }
        }
    }
}

static inline int smem_bytes(int K) {
    return (K * H + TILE_M * SAS + H) * (int)sizeof(float);
}

extern "C" void kernel_launch(void* const* d_in, const int* in_sizes, int n_in,
                              void* d_out, int out_size) {
    const float* x     = (const float*)d_in[0];
    const void*  eidx  = d_in[1];
    const float* eattr = (const float*)d_in[2];
    const float* We1   = (const float*)d_in[3];
    const float* be1   = (const float*)d_in[4];
    const float* We2   = (const float*)d_in[5];
    const float* be2   = (const float*)d_in[6];
    const float* Wn1   = (const float*)d_in[7];
    const float* bn1   = (const float*)d_in[8];
    const float* Wn2   = (const float*)d_in[9];
    const float* bn2   = (const float*)d_in[10];
    float* out = (float*)d_out;

    const int N = in_sizes[0] / H;
    const int E = in_sizes[1] / 2;   // element count of edge_index is 2*E
                                     // (independent of int32/int64 -- detected on device)

    cudaFuncSetAttribute(gemm_kernel<384, 0>, cudaFuncAttributeMaxDynamicSharedMemorySize, smem_bytes(384));
    cudaFuncSetAttribute(gemm_kernel<128, 1>, cudaFuncAttributeMaxDynamicSharedMemorySize, smem_bytes(128));
    cudaFuncSetAttribute(gemm_kernel<256, 2>, cudaFuncAttributeMaxDynamicSharedMemorySize, smem_bytes(256));
    cudaFuncSetAttribute(gemm_kernel<128, 3>, cudaFuncAttributeMaxDynamicSharedMemorySize, smem_bytes(128));

    detect_idx_kernel<<<1, 1>>>((const unsigned int*)eidx);

    const int n4 = N * H / 4;
    zero_agg_kernel<<<(n4 + 255) / 256, 256>>>(n4);

    // Edge MLP layer 1: [E,384] @ We1 -> ReLU -> g_hid   (weights 196KB smem, 1 blk/SM)
    gemm_kernel<384, 0><<<152, THREADS, smem_bytes(384)>>>(x, eattr, eidx, We1, be1, nullptr, E, E);
    // Edge MLP layer 2 + scatter-add into g_agg
    gemm_kernel<128, 1><<<304, THREADS, smem_bytes(128)>>>(x, eattr, eidx, We2, be2, nullptr, E, E);
    // Node MLP layer 1: [N,256] @ Wn1 -> ReLU -> g_hid (reused)
    gemm_kernel<256, 2><<<152, THREADS, smem_bytes(256)>>>(x, eattr, eidx, Wn1, bn1, nullptr, N, E);
    // Node MLP layer 2 -> d_out
    gemm_kernel<128, 3><<<304, THREADS, smem_bytes(128)>>>(x, eattr, eidx, Wn2, bn2, out, N, E);
}

// round 3
// speedup vs baseline: 5.0066x; 5.0066x over previous
#include <cuda_runtime.h>
#include <cstdint>

#define H     128
#define MAX_N 50000
#define MAX_E 800000

// ---------------------------------------------------------------------------
// Scratch (device globals: no allocations allowed)
// ---------------------------------------------------------------------------
__device__ float g_agg[MAX_N * H];            // 25.6 MB scatter target
__device__ float g_We1img[12 * 4096];         // pre-swizzled tf32 weight images
__device__ float g_We2img[4  * 4096];
__device__ float g_Wn1img[8  * 4096];
__device__ float g_Wn2img[4  * 4096];
__device__ int   g_is64;

// ---------------------------------------------------------------------------
// helpers
// ---------------------------------------------------------------------------
__device__ __forceinline__ uint32_t smem_u32(const void* p) {
    uint32_t a;
    asm("{ .reg .u64 t; cvta.to.shared.u64 t, %1; cvt.u32.u64 %0, t; }" : "=r"(a) : "l"(p));
    return a;
}
__device__ __forceinline__ void cp16(uint32_t dst, const void* src, uint32_t sz) {
    asm volatile("cp.async.ca.shared.global [%0], [%1], 16, %2;"
                 :: "r"(dst), "l"(src), "r"(sz) : "memory");
}
#define CP_COMMIT() asm volatile("cp.async.commit_group;" ::: "memory")
#define CP_WAIT(n)  asm volatile("cp.async.wait_group %0;" :: "n"(n) : "memory")

__device__ __forceinline__ uint32_t cvt_tf32(float v) {
    uint32_t r; asm("cvt.rna.tf32.f32 %0, %1;" : "=r"(r) : "f"(v)); return r;
}
__device__ __forceinline__ void mma8(float* c, const uint32_t* a, const uint32_t* b) {
    asm volatile("mma.sync.aligned.m16n8k8.row.col.f32.tf32.tf32.f32 "
        "{%0,%1,%2,%3},{%4,%5,%6,%7},{%8,%9},{%0,%1,%2,%3};"
        : "+f"(c[0]), "+f"(c[1]), "+f"(c[2]), "+f"(c[3])
        : "r"(a[0]), "r"(a[1]), "r"(a[2]), "r"(a[3]), "r"(b[0]), "r"(b[1]));
}

// ---------------------------------------------------------------------------
// prep kernels
// ---------------------------------------------------------------------------
__global__ void detect_idx_kernel(const unsigned int* __restrict__ e) {
    g_is64 = (e[1] == 0u && e[3] == 0u && e[5] == 0u && e[7] == 0u) ? 1 : 0;
}
__global__ void zero_agg_kernel(int n4) {
    int i = blockIdx.x * blockDim.x + threadIdx.x;
    if (i < n4) ((float4*)g_agg)[i] = make_float4(0.f, 0.f, 0.f, 0.f);
}
// weight image: chunk c covers k=c*32..c*32+31; layout [kk][n ^ 8*(kk&3)], tf32(rna)
__global__ void prep_w_kernel(const float* __restrict__ W, int which, int nch) {
    float* img = (which == 0) ? g_We1img : (which == 1) ? g_We2img
               : (which == 2) ? g_Wn1img : g_Wn2img;
    int idx = blockIdx.x * blockDim.x + threadIdx.x;
    if (idx >= nch * 4096) return;
    int c = idx >> 12, rem = idx & 4095, kk = rem >> 7, n = rem & 127;
    float v = W[(c * 32 + kk) * H + n];
    ((uint32_t*)img)[c * 4096 + kk * 128 + (n ^ ((kk & 3) << 3))] = cvt_tf32(v);
}

// ---------------------------------------------------------------------------
// Fused 2-layer MLP, tf32 mma.sync, 128x128 tiles, 8 warps (4M x 2N, 32x64 each)
// MODE 0 (edge, NCH1=12): A = concat(x[row], x[col], eattr); L1->ReLU->L2;
//                         red.v4 scatter into g_agg[col]
// MODE 1 (node, NCH1=8):  A = concat(x, g_agg); L1->ReLU->L2; store to out
// smem floats: sA[2][4096] | sB[2][4096] | sW2[16384] | sHid/Msg[17408] = 50176
// ---------------------------------------------------------------------------
template<int NCH1, int MODE>
__global__ void __launch_bounds__(256, 1)
fused_kernel(const float* __restrict__ x, const float* __restrict__ eattr,
             const void* __restrict__ eidx, const float* __restrict__ b1v,
             const float* __restrict__ b2v, float* __restrict__ outp,
             int M, int E)
{
    extern __shared__ __align__(16) float sm[];
    uint32_t* const smu = (uint32_t*)sm;
    float* const sW2  = sm + 16384;
    float* const sHid = sm + 32768;      // also reused as Msg (row stride 136)
    __shared__ int   sRow[128], sCol[128];
    __shared__ float sB1[128], sB2[128];

    const int tid  = threadIdx.x;
    const int lane = tid & 31, warp = tid >> 5;
    const int g = lane >> 2, t = lane & 3;
    const int wM = warp & 3, wN = warp >> 2;

    { // persistent W2 image
        const float4* s4 = (const float4*)((MODE == 0) ? g_We2img : g_Wn2img);
        float4* d4 = (float4*)sW2;
        #pragma unroll
        for (int i = 0; i < 16; i++) d4[tid + i * 256] = s4[tid + i * 256];
    }
    if (tid < 128) { sB1[tid] = b1v[tid]; sB2[tid] = b2v[tid]; }
    const int is64v = g_is64;
    const float* W1img = (MODE == 0) ? g_We1img : g_Wn1img;
    __syncthreads();

    const int rA0  = wM * 32 + g;
    const int axor = g << 2;
    int nswz[8];
    #pragma unroll
    for (int jn = 0; jn < 8; jn++) nswz[jn] = (wN * 64 + jn * 8 + g) ^ (t << 3);

    const int ar    = tid >> 1;   // staging row
    const int halfA = tid & 1;

    const int ntiles = (M + 127) >> 7;
    for (int tile = blockIdx.x; tile < ntiles; tile += gridDim.x) {
        const int mbase = tile << 7;
        __syncthreads();            // Msg readers of prev tile done; sCol safe
        if (MODE == 0 && tid < 128) {
            int e = mbase + tid; int rI = 0, cI = 0;
            if (e < M) {
                if (is64v) {
                    const long long* p = (const long long*)eidx;
                    rI = (int)p[e]; cI = (int)p[(long long)E + e];
                } else {
                    const int* p = (const int*)eidx;
                    rI = p[e]; cI = p[E + e];
                }
            }
            sRow[tid] = rI; sCol[tid] = cI;
        }
        __syncthreads();

        auto stage = [&](int c) {
            bool valid = (mbase + ar) < M;
            int srow; const float* basep;
            if (MODE == 0) {
                int seg = c >> 2;
                srow = (seg == 0) ? sRow[ar] : (seg == 1) ? sCol[ar] : (mbase + ar);
                basep = (seg == 2) ? eattr : x;
            } else {
                srow = valid ? (mbase + ar) : 0;
                basep = (c >= 4) ? g_agg : x;
            }
            const float* srcA = basep + (size_t)srow * H + (c & 3) * 32 + halfA * 16;
            uint32_t dstA = smem_u32(sm + (c & 1) * 4096 + ar * 32);
            uint32_t sz = valid ? 16u : 0u;
            #pragma unroll
            for (int i = 0; i < 4; i++) {
                int q  = halfA * 4 + i;
                int qs = q ^ (ar & 7);
                cp16(dstA + qs * 16, srcA + i * 4, sz);
            }
            const float4* srcB = (const float4*)(W1img + c * 4096) + tid;
            uint32_t dstB = smem_u32(sm + 8192 + (c & 1) * 4096) + tid * 16;
            #pragma unroll
            for (int i = 0; i < 4; i++) cp16(dstB + i * 4096, srcB + i * 256, 16);
            CP_COMMIT();
        };

        float acc[2][8][4];
        #pragma unroll
        for (int mt = 0; mt < 2; mt++)
            #pragma unroll
            for (int jn = 0; jn < 8; jn++)
                #pragma unroll
                for (int i = 0; i < 4; i++) acc[mt][jn][i] = 0.f;

        stage(0); stage(1);

        auto kstep = [&](const float* A, const uint32_t* B, int ks) {
            uint32_t af[2][4];
            const int kb0 = ks * 8 + t;
            #pragma unroll
            for (int mt = 0; mt < 2; mt++) {
                const int ra = rA0 + mt * 16;
                af[mt][0] = cvt_tf32(A[ra * 32 + (kb0 ^ axor)]);
                af[mt][1] = cvt_tf32(A[(ra + 8) * 32 + (kb0 ^ axor)]);
                af[mt][2] = cvt_tf32(A[ra * 32 + ((kb0 + 4) ^ axor)]);
                af[mt][3] = cvt_tf32(A[(ra + 8) * 32 + ((kb0 + 4) ^ axor)]);
            }
            #pragma unroll
            for (int jn = 0; jn < 8; jn++) {
                uint32_t bf[2];
                bf[0] = B[kb0 * 128 + nswz[jn]];
                bf[1] = B[(kb0 + 4) * 128 + nswz[jn]];
                mma8(acc[0][jn], af[0], bf);
                mma8(acc[1][jn], af[1], bf);
            }
        };

        // ----------------------------- L1 -------------------------------
        #pragma unroll
        for (int c = 0; c < NCH1; c++) {
            if (c < NCH1 - 1) { CP_WAIT(1); } else { CP_WAIT(0); }
            __syncthreads();
            const float*    A = sm  + (c & 1) * 4096;
            const uint32_t* B = smu + 8192 + (c & 1) * 4096;
            #pragma unroll
            for (int ks = 0; ks < 4; ks++) kstep(A, B, ks);
            __syncthreads();
            if (c + 2 < NCH1) stage(c + 2);
        }

        // -------- hidden = relu(acc + b1) -> tf32 -> sHid (A-layout) ------
        #pragma unroll
        for (int mt = 0; mt < 2; mt++)
        #pragma unroll
        for (int jn = 0; jn < 8; jn++) {
            int col0 = wN * 64 + jn * 8 + 2 * t;
            float b0 = sB1[col0], b1 = sB1[col0 + 1];
            uint32_t u0 = cvt_tf32(fmaxf(acc[mt][jn][0] + b0, 0.f));
            uint32_t u1 = cvt_tf32(fmaxf(acc[mt][jn][1] + b1, 0.f));
            uint32_t u2 = cvt_tf32(fmaxf(acc[mt][jn][2] + b0, 0.f));
            uint32_t u3 = cvt_tf32(fmaxf(acc[mt][jn][3] + b1, 0.f));
            int slab = col0 >> 5, kk = col0 & 31;
            uint32_t* dst = (uint32_t*)(sHid + slab * 4096);
            int ra = rA0 + mt * 16;
            *(uint2*)(dst + ra * 32 + (kk ^ axor))       = make_uint2(u0, u1);
            *(uint2*)(dst + (ra + 8) * 32 + (kk ^ axor)) = make_uint2(u2, u3);
            acc[mt][jn][0] = acc[mt][jn][1] = acc[mt][jn][2] = acc[mt][jn][3] = 0.f;
        }
        __syncthreads();

        // ----------------------------- L2 (K=128) ------------------------
        #pragma unroll
        for (int ks16 = 0; ks16 < 16; ks16++) {
            const float*    A = sHid + (ks16 >> 2) * 4096;
            const uint32_t* B = (const uint32_t*)(sW2 + (ks16 >> 2) * 4096);
            kstep(A, B, ks16 & 3);
        }
        __syncthreads();   // all reads of sHid done before Msg overwrite

        // ------- messages/out -> Msg buffer (row stride 136, +4 pad) ------
        float* Msg = sHid;
        #pragma unroll
        for (int mt = 0; mt < 2; mt++)
        #pragma unroll
        for (int jn = 0; jn < 8; jn++) {
            int col0 = wN * 64 + jn * 8 + 2 * t;
            float b0 = sB2[col0], b1 = sB2[col0 + 1];
            int cadj = col0 + ((col0 >> 6) << 2);
            int ra = rA0 + mt * 16;
            *(float2*)(Msg + ra * 136 + cadj) =
                make_float2(acc[mt][jn][0] + b0, acc[mt][jn][1] + b1);
            *(float2*)(Msg + (ra + 8) * 136 + cadj) =
                make_float2(acc[mt][jn][2] + b0, acc[mt][jn][3] + b1);
        }
        __syncthreads();

        // --------------------- scatter / store rows ----------------------
        if (mbase + ar < M) {
            const float* srcr = Msg + ar * 136 + halfA * 68;
            if (MODE == 0) {
                float* dst = g_agg + (size_t)sCol[ar] * H + halfA * 64;
                #pragma unroll
                for (int q = 0; q < 16; q++) {
                    float4 v = *(const float4*)(srcr + q * 4);
                    asm volatile("red.global.add.v4.f32 [%0], {%1, %2, %3, %4};"
                                 :: "l"(dst + q * 4), "f"(v.x), "f"(v.y), "f"(v.z), "f"(v.w)
                                 : "memory");
                }
            } else {
                float4* dst = (float4*)(outp + (size_t)(mbase + ar) * H + halfA * 64);
                #pragma unroll
                for (int q = 0; q < 16; q++) dst[q] = *(const float4*)(srcr + q * 4);
            }
        }
    }
}

// ---------------------------------------------------------------------------
#define DYN_SMEM (50176 * 4)   // 200704 bytes

extern "C" void kernel_launch(void* const* d_in, const int* in_sizes, int n_in,
                              void* d_out, int out_size) {
    const float* x     = (const float*)d_in[0];
    const void*  eidx  = d_in[1];
    const float* eattr = (const float*)d_in[2];
    const float* We1   = (const float*)d_in[3];
    const float* be1   = (const float*)d_in[4];
    const float* We2   = (const float*)d_in[5];
    const float* be2   = (const float*)d_in[6];
    const float* Wn1   = (const float*)d_in[7];
    const float* bn1   = (const float*)d_in[8];
    const float* Wn2   = (const float*)d_in[9];
    const float* bn2   = (const float*)d_in[10];
    float* out = (float*)d_out;

    const int N = in_sizes[0] / H;
    const int E = in_sizes[1] / 2;

    cudaFuncSetAttribute(fused_kernel<12, 0>, cudaFuncAttributeMaxDynamicSharedMemorySize, DYN_SMEM);
    cudaFuncSetAttribute(fused_kernel<8, 1>,  cudaFuncAttributeMaxDynamicSharedMemorySize, DYN_SMEM);

    detect_idx_kernel<<<1, 1>>>((const unsigned int*)eidx);

    prep_w_kernel<<<(12 * 4096 + 255) / 256, 256>>>(We1, 0, 12);
    prep_w_kernel<<<(4  * 4096 + 255) / 256, 256>>>(We2, 1, 4);
    prep_w_kernel<<<(8  * 4096 + 255) / 256, 256>>>(Wn1, 2, 8);
    prep_w_kernel<<<(4  * 4096 + 255) / 256, 256>>>(Wn2, 3, 4);

    const int n4 = N * H / 4;
    zero_agg_kernel<<<(n4 + 255) / 256, 256>>>(n4);

    // Edge phase: gather -> MLP(384->128->128) -> red.v4 scatter into g_agg
    fused_kernel<12, 0><<<152, 256, DYN_SMEM>>>(x, eattr, eidx, be1, be2, nullptr, E, E);
    // Node phase: concat(x, agg) -> MLP(256->128->128) -> out
    fused_kernel<8, 1><<<152, 256, DYN_SMEM>>>(x, eattr, eidx, bn1, bn2, out, N, E);
}

// round 4
// speedup vs baseline: 5.6162x; 1.1218x over previous
#include <cuda_runtime.h>
#include <cstdint>

#define H     128
#define MAX_N 50000
#define MAX_E 800000
#define NPAD  50048

// ---------------------------------------------------------------------------
// Scratch (device globals: no allocations allowed)
// ---------------------------------------------------------------------------
__device__ float g_agg[NPAD * H];          // scatter target
__device__ float g_Pa[NPAD * H];           // x @ Wa + be1   (per-node, edge L1 row term)
__device__ float g_Pb[NPAD * H];           // x @ Wb         (per-node, edge L1 col term)
__device__ float g_R [NPAD * H];           // x @ Wn1_top + bn1 (node L1 x-term)
// tf32 pre-swizzled weight images, 4 chunks of 4096 floats each
__device__ float g_Wa[16384], g_Wb[16384], g_Wc[16384];
__device__ float g_We2img[16384];
__device__ float g_Wn1t[16384], g_Wn1b[16384], g_Wn2img[16384];
__device__ float g_zero[H];                // stays zero
__device__ int   g_is64;

// ---------------------------------------------------------------------------
// helpers
// ---------------------------------------------------------------------------
__device__ __forceinline__ uint32_t smem_u32(const void* p) {
    uint32_t a;
    asm("{ .reg .u64 t; cvta.to.shared.u64 t, %1; cvt.u32.u64 %0, t; }" : "=r"(a) : "l"(p));
    return a;
}
__device__ __forceinline__ void cp16(uint32_t dst, const void* src, uint32_t sz) {
    asm volatile("cp.async.ca.shared.global [%0], [%1], 16, %2;"
                 :: "r"(dst), "l"(src), "r"(sz) : "memory");
}
#define CP_COMMIT() asm volatile("cp.async.commit_group;" ::: "memory")
#define CP_WAIT(n)  asm volatile("cp.async.wait_group %0;" :: "n"(n) : "memory")

__device__ __forceinline__ uint32_t cvt_tf32(float v) {
    uint32_t r; asm("cvt.rna.tf32.f32 %0, %1;" : "=r"(r) : "f"(v)); return r;
}
__device__ __forceinline__ void mma8(float* c, const uint32_t* a, const uint32_t* b) {
    asm volatile("mma.sync.aligned.m16n8k8.row.col.f32.tf32.tf32.f32 "
        "{%0,%1,%2,%3},{%4,%5,%6,%7},{%8,%9},{%0,%1,%2,%3};"
        : "+f"(c[0]), "+f"(c[1]), "+f"(c[2]), "+f"(c[3])
        : "r"(a[0]), "r"(a[1]), "r"(a[2]), "r"(a[3]), "r"(b[0]), "r"(b[1]));
}

// ---------------------------------------------------------------------------
// prep kernels
// ---------------------------------------------------------------------------
__global__ void detect_idx_kernel(const unsigned int* __restrict__ e) {
    g_is64 = (e[1] == 0u && e[3] == 0u && e[5] == 0u && e[7] == 0u) ? 1 : 0;
}
__global__ void zero_agg_kernel(int n4) {
    int i = blockIdx.x * blockDim.x + threadIdx.x;
    if (i < n4) ((float4*)g_agg)[i] = make_float4(0.f, 0.f, 0.f, 0.f);
}
// image of W[row_off + k][n] for k in [0,128): chunk c: [kk][n ^ 8*(kk&3)], tf32(rna)
__global__ void prep_w_kernel(const float* __restrict__ W, int row_off, int which) {
    float* img = (which == 0) ? g_Wa : (which == 1) ? g_Wb : (which == 2) ? g_Wc
               : (which == 3) ? g_We2img : (which == 4) ? g_Wn1t
               : (which == 5) ? g_Wn1b : g_Wn2img;
    int idx = blockIdx.x * blockDim.x + threadIdx.x;
    if (idx >= 16384) return;
    int c = idx >> 12, rem = idx & 4095, kk = rem >> 7, n = rem & 127;
    float v = W[(size_t)(row_off + c * 32 + kk) * H + n];
    ((uint32_t*)img)[c * 4096 + kk * 128 + (n ^ ((kk & 3) << 3))] = cvt_tf32(v);
}

// ===========================================================================
// Shared tile machinery: 128x128 tile, 8 warps (4M x 2N), tf32 mma.sync
// ===========================================================================
struct TileCtx {
    int lane, warp, g, t, wM, wN, rA0, axor, ar, halfA;
    int nswz[8];
    __device__ __forceinline__ void init(int tid) {
        lane = tid & 31; warp = tid >> 5;
        g = lane >> 2; t = lane & 3;
        wM = warp & 3; wN = warp >> 2;
        rA0 = wM * 32 + g; axor = g << 2;
        ar = tid >> 1; halfA = tid & 1;
        #pragma unroll
        for (int jn = 0; jn < 8; jn++) nswz[jn] = (wN * 64 + jn * 8 + g) ^ (t << 3);
    }
};

#define KSTEP(A, B, ks) do {                                                  \
    uint32_t af[2][4];                                                        \
    const int kb0 = (ks) * 8 + cx.t;                                          \
    _Pragma("unroll")                                                         \
    for (int mt = 0; mt < 2; mt++) {                                          \
        const int ra = cx.rA0 + mt * 16;                                      \
        af[mt][0] = cvt_tf32((A)[ra * 32 + (kb0 ^ cx.axor)]);                 \
        af[mt][1] = cvt_tf32((A)[(ra + 8) * 32 + (kb0 ^ cx.axor)]);           \
        af[mt][2] = cvt_tf32((A)[ra * 32 + ((kb0 + 4) ^ cx.axor)]);           \
        af[mt][3] = cvt_tf32((A)[(ra + 8) * 32 + ((kb0 + 4) ^ cx.axor)]);     \
    }                                                                         \
    _Pragma("unroll")                                                         \
    for (int jn = 0; jn < 8; jn++) {                                          \
        uint32_t bf[2];                                                       \
        bf[0] = (B)[kb0 * 128 + cx.nswz[jn]];                                 \
        bf[1] = (B)[(kb0 + 4) * 128 + cx.nswz[jn]];                           \
        mma8(acc[0][jn], af[0], bf);                                          \
        mma8(acc[1][jn], af[1], bf);                                          \
    }                                                                         \
} while (0)

// ---------------------------------------------------------------------------
// Precompute GEMM: out = x @ Wimg + bias   for 3 weight images (Pa, Pb, R)
// smem: A 2x4096 | B 2x4096 | Msg 17408   = 33792 floats
// ---------------------------------------------------------------------------
__global__ void __launch_bounds__(256, 1)
precompute_kernel(const float* __restrict__ x, const float* __restrict__ be1,
                  const float* __restrict__ bn1, int M)
{
    extern __shared__ __align__(16) float sm[];
    uint32_t* const smu = (uint32_t*)sm;
    float* const Msg = sm + 16384;
    __shared__ float sB[128];

    const int tid = threadIdx.x;
    TileCtx cx; cx.init(tid);

    const int T = (M + 127) >> 7;
    for (int v = blockIdx.x; v < 3 * T; v += gridDim.x) {
        const int which = v / T;
        const int mbase = (v % T) << 7;
        __syncthreads();
        const float* W1img = (which == 0) ? g_Wa : (which == 1) ? g_Wb : g_Wn1t;
        const float* bias  = (which == 0) ? be1 : (which == 1) ? g_zero : bn1;
        float* outp        = (which == 0) ? g_Pa : (which == 1) ? g_Pb : g_R;
        if (tid < 128) sB[tid] = bias[tid];

        auto stage = [&](int c) {
            bool valid = (mbase + cx.ar) < M;
            const float* srcA = x + (size_t)(valid ? (mbase + cx.ar) : 0) * H
                              + (c & 3) * 32 + cx.halfA * 16;
            uint32_t dstA = smem_u32(sm + (c & 1) * 4096 + cx.ar * 32);
            uint32_t sz = valid ? 16u : 0u;
            #pragma unroll
            for (int i = 0; i < 4; i++) {
                int q = cx.halfA * 4 + i, qs = q ^ (cx.ar & 7);
                cp16(dstA + qs * 16, srcA + i * 4, sz);
            }
            const float4* srcB = (const float4*)(W1img + c * 4096) + tid;
            uint32_t dstB = smem_u32(sm + 8192 + (c & 1) * 4096) + tid * 16;
            #pragma unroll
            for (int i = 0; i < 4; i++) cp16(dstB + i * 4096, srcB + i * 256, 16);
            CP_COMMIT();
        };

        float acc[2][8][4];
        #pragma unroll
        for (int mt = 0; mt < 2; mt++)
            #pragma unroll
            for (int jn = 0; jn < 8; jn++)
                #pragma unroll
                for (int i = 0; i < 4; i++) acc[mt][jn][i] = 0.f;

        stage(0); stage(1);
        #pragma unroll
        for (int c = 0; c < 4; c++) {
            if (c < 3) { CP_WAIT(1); } else { CP_WAIT(0); }
            __syncthreads();
            const float*    A = sm  + (c & 1) * 4096;
            const uint32_t* B = smu + 8192 + (c & 1) * 4096;
            #pragma unroll
            for (int ks = 0; ks < 4; ks++) KSTEP(A, B, ks);
            __syncthreads();
            if (c + 2 < 4) stage(c + 2);
        }

        #pragma unroll
        for (int mt = 0; mt < 2; mt++)
        #pragma unroll
        for (int jn = 0; jn < 8; jn++) {
            int col0 = cx.wN * 64 + jn * 8 + 2 * cx.t;
            float b0 = sB[col0], b1 = sB[col0 + 1];
            int cadj = col0 + ((col0 >> 6) << 2);
            int ra = cx.rA0 + mt * 16;
            *(float2*)(Msg + ra * 136 + cadj) =
                make_float2(acc[mt][jn][0] + b0, acc[mt][jn][1] + b1);
            *(float2*)(Msg + (ra + 8) * 136 + cadj) =
                make_float2(acc[mt][jn][2] + b0, acc[mt][jn][3] + b1);
        }
        __syncthreads();
        if (mbase + cx.ar < M) {
            const float* srcr = Msg + cx.ar * 136 + cx.halfA * 68;
            float4* dst = (float4*)(outp + (size_t)(mbase + cx.ar) * H + cx.halfA * 64);
            #pragma unroll
            for (int q = 0; q < 16; q++) dst[q] = *(const float4*)(srcr + q * 4);
        }
    }
}

// ---------------------------------------------------------------------------
// Fused phase kernel.
// MODE 0 (edge): Q = eattr @ Wc; hid = relu(Q + Pa[row] + Pb[col]);
//                msg = hid @ We2 + be2; red.v4 scatter into g_agg[col]
// MODE 1 (node): Q = agg @ Wn1b; hid = relu(Q + R[m]);
//                out = hid @ Wn2 + bn2
// smem floats: A 2x4096 | B 2x4096 | sW2 16384 | sHid/Msg 17408 = 50176
// ---------------------------------------------------------------------------
template<int MODE>
__global__ void __launch_bounds__(256, 1)
fused_kernel(const float* __restrict__ eattr, const void* __restrict__ eidx,
             const float* __restrict__ b2v, float* __restrict__ outp,
             int M, int E)
{
    extern __shared__ __align__(16) float sm[];
    uint32_t* const smu = (uint32_t*)sm;
    float* const sW2  = sm + 16384;
    float* const sHid = sm + 32768;
    __shared__ int   sRow[128], sCol[128];
    __shared__ float sB2[128];

    const int tid = threadIdx.x;
    TileCtx cx; cx.init(tid);

    { // persistent L2 weight image
        const float4* s4 = (const float4*)((MODE == 0) ? g_We2img : g_Wn2img);
        float4* d4 = (float4*)sW2;
        #pragma unroll
        for (int i = 0; i < 16; i++) d4[tid + i * 256] = s4[tid + i * 256];
    }
    if (tid < 128) sB2[tid] = b2v[tid];
    const int is64v = g_is64;
    const float* W1img = (MODE == 0) ? g_Wc : g_Wn1b;
    const float* Asrc  = (MODE == 0) ? eattr : g_agg;
    __syncthreads();

    const int ntiles = (M + 127) >> 7;
    for (int tile = blockIdx.x; tile < ntiles; tile += gridDim.x) {
        const int mbase = tile << 7;
        __syncthreads();
        if (MODE == 0 && tid < 128) {
            int e = mbase + tid; int rI = 0, cI = 0;
            if (e < M) {
                if (is64v) {
                    const long long* p = (const long long*)eidx;
                    rI = (int)p[e]; cI = (int)p[(long long)E + e];
                } else {
                    const int* p = (const int*)eidx;
                    rI = p[e]; cI = p[E + e];
                }
            }
            sRow[tid] = rI; sCol[tid] = cI;
        }
        __syncthreads();

        auto stage = [&](int c) {
            bool valid = (mbase + cx.ar) < M;
            const float* srcA = Asrc + (size_t)(valid ? (mbase + cx.ar) : 0) * H
                              + (c & 3) * 32 + cx.halfA * 16;
            uint32_t dstA = smem_u32(sm + (c & 1) * 4096 + cx.ar * 32);
            uint32_t sz = valid ? 16u : 0u;
            #pragma unroll
            for (int i = 0; i < 4; i++) {
                int q = cx.halfA * 4 + i, qs = q ^ (cx.ar & 7);
                cp16(dstA + qs * 16, srcA + i * 4, sz);
            }
            const float4* srcB = (const float4*)(W1img + c * 4096) + tid;
            uint32_t dstB = smem_u32(sm + 8192 + (c & 1) * 4096) + tid * 16;
            #pragma unroll
            for (int i = 0; i < 4; i++) cp16(dstB + i * 4096, srcB + i * 256, 16);
            CP_COMMIT();
        };

        float acc[2][8][4];
        #pragma unroll
        for (int mt = 0; mt < 2; mt++)
            #pragma unroll
            for (int jn = 0; jn < 8; jn++)
                #pragma unroll
                for (int i = 0; i < 4; i++) acc[mt][jn][i] = 0.f;

        stage(0); stage(1);
        // ------------------ L1: Q GEMM, K=128 (4 chunks) -------------------
        #pragma unroll
        for (int c = 0; c < 4; c++) {
            if (c < 3) { CP_WAIT(1); } else { CP_WAIT(0); }
            __syncthreads();
            const float*    A = sm  + (c & 1) * 4096;
            const uint32_t* B = smu + 8192 + (c & 1) * 4096;
            #pragma unroll
            for (int ks = 0; ks < 4; ks++) KSTEP(A, B, ks);
            __syncthreads();
            if (c + 2 < 4) stage(c + 2);
        }

        // ---------- add gathered per-node terms, relu -> sHid --------------
        #pragma unroll
        for (int mt = 0; mt < 2; mt++) {
            const int r0r = cx.rA0 + mt * 16, r8r = r0r + 8;
            int ia0, ia8, ic0 = 0, ic8 = 0;
            if (MODE == 0) {
                ia0 = sRow[r0r]; ic0 = sCol[r0r];
                ia8 = sRow[r8r]; ic8 = sCol[r8r];
            } else {
                ia0 = min(mbase + r0r, M - 1);
                ia8 = min(mbase + r8r, M - 1);
            }
            const float* PaB = (MODE == 0) ? g_Pa : g_R;
            #pragma unroll
            for (int jn = 0; jn < 8; jn++) {
                int col0 = cx.wN * 64 + jn * 8 + 2 * cx.t;
                float2 pa0 = *(const float2*)(PaB + (size_t)ia0 * H + col0);
                float2 pa8 = *(const float2*)(PaB + (size_t)ia8 * H + col0);
                float v0 = acc[mt][jn][0] + pa0.x, v1 = acc[mt][jn][1] + pa0.y;
                float v2 = acc[mt][jn][2] + pa8.x, v3 = acc[mt][jn][3] + pa8.y;
                if (MODE == 0) {
                    float2 pb0 = *(const float2*)(g_Pb + (size_t)ic0 * H + col0);
                    float2 pb8 = *(const float2*)(g_Pb + (size_t)ic8 * H + col0);
                    v0 += pb0.x; v1 += pb0.y; v2 += pb8.x; v3 += pb8.y;
                }
                uint32_t u0 = cvt_tf32(fmaxf(v0, 0.f));
                uint32_t u1 = cvt_tf32(fmaxf(v1, 0.f));
                uint32_t u2 = cvt_tf32(fmaxf(v2, 0.f));
                uint32_t u3 = cvt_tf32(fmaxf(v3, 0.f));
                int slab = col0 >> 5, kk = col0 & 31;
                uint32_t* dst = (uint32_t*)(sHid + slab * 4096);
                *(uint2*)(dst + r0r * 32 + (kk ^ cx.axor)) = make_uint2(u0, u1);
                *(uint2*)(dst + r8r * 32 + (kk ^ cx.axor)) = make_uint2(u2, u3);
                acc[mt][jn][0] = acc[mt][jn][1] = acc[mt][jn][2] = acc[mt][jn][3] = 0.f;
            }
        }
        __syncthreads();

        // ------------------------- L2 (K=128) ------------------------------
        #pragma unroll
        for (int ks16 = 0; ks16 < 16; ks16++) {
            const float*    A = sHid + (ks16 >> 2) * 4096;
            const uint32_t* B = (const uint32_t*)(sW2 + (ks16 >> 2) * 4096);
            KSTEP(A, B, ks16 & 3);
        }
        __syncthreads();

        // ---------------- bias2 -> Msg (stride 136) ------------------------
        float* Msg = sHid;
        #pragma unroll
        for (int mt = 0; mt < 2; mt++)
        #pragma unroll
        for (int jn = 0; jn < 8; jn++) {
            int col0 = cx.wN * 64 + jn * 8 + 2 * cx.t;
            float b0 = sB2[col0], b1 = sB2[col0 + 1];
            int cadj = col0 + ((col0 >> 6) << 2);
            int ra = cx.rA0 + mt * 16;
            *(float2*)(Msg + ra * 136 + cadj) =
                make_float2(acc[mt][jn][0] + b0, acc[mt][jn][1] + b1);
            *(float2*)(Msg + (ra + 8) * 136 + cadj) =
                make_float2(acc[mt][jn][2] + b0, acc[mt][jn][3] + b1);
        }
        __syncthreads();

        // --------------------- scatter / store rows ------------------------
        if (mbase + cx.ar < M) {
            const float* srcr = Msg + cx.ar * 136 + cx.halfA * 68;
            if (MODE == 0) {
                float* dst = g_agg + (size_t)sCol[cx.ar] * H + cx.halfA * 64;
                #pragma unroll
                for (int q = 0; q < 16; q++) {
                    float4 v = *(const float4*)(srcr + q * 4);
                    asm volatile("red.global.add.v4.f32 [%0], {%1, %2, %3, %4};"
                                 :: "l"(dst + q * 4), "f"(v.x), "f"(v.y), "f"(v.z), "f"(v.w)
                                 : "memory");
                }
            } else {
                float4* dst = (float4*)(outp + (size_t)(mbase + cx.ar) * H + cx.halfA * 64);
                #pragma unroll
                for (int q = 0; q < 16; q++) dst[q] = *(const float4*)(srcr + q * 4);
            }
        }
    }
}

// ---------------------------------------------------------------------------
#define DYN_FUSED (50176 * 4)
#define DYN_PRE   (33792 * 4)

extern "C" void kernel_launch(void* const* d_in, const int* in_sizes, int n_in,
                              void* d_out, int out_size) {
    const float* x     = (const float*)d_in[0];
    const void*  eidx  = d_in[1];
    const float* eattr = (const float*)d_in[2];
    const float* We1   = (const float*)d_in[3];
    const float* be1   = (const float*)d_in[4];
    const float* We2   = (const float*)d_in[5];
    const float* be2   = (const float*)d_in[6];
    const float* Wn1   = (const float*)d_in[7];
    const float* bn1   = (const float*)d_in[8];
    const float* Wn2   = (const float*)d_in[9];
    const float* bn2   = (const float*)d_in[10];
    float* out = (float*)d_out;

    const int N = in_sizes[0] / H;
    const int E = in_sizes[1] / 2;

    cudaFuncSetAttribute(fused_kernel<0>, cudaFuncAttributeMaxDynamicSharedMemorySize, DYN_FUSED);
    cudaFuncSetAttribute(fused_kernel<1>, cudaFuncAttributeMaxDynamicSharedMemorySize, DYN_FUSED);
    cudaFuncSetAttribute(precompute_kernel, cudaFuncAttributeMaxDynamicSharedMemorySize, DYN_PRE);

    detect_idx_kernel<<<1, 1>>>((const unsigned int*)eidx);

    // weight images: We1 = [Wa; Wb; Wc] (row blocks), Wn1 = [Wn1t; Wn1b]
    prep_w_kernel<<<64, 256>>>(We1,   0, 0);   // Wa
    prep_w_kernel<<<64, 256>>>(We1, 128, 1);   // Wb
    prep_w_kernel<<<64, 256>>>(We1, 256, 2);   // Wc
    prep_w_kernel<<<64, 256>>>(We2,   0, 3);
    prep_w_kernel<<<64, 256>>>(Wn1,   0, 4);   // Wn1 top
    prep_w_kernel<<<64, 256>>>(Wn1, 128, 5);   // Wn1 bottom
    prep_w_kernel<<<64, 256>>>(Wn2,   0, 6);

    const int n4 = N * H / 4;
    zero_agg_kernel<<<(n4 + 255) / 256, 256>>>(n4);

    // Pa = x@Wa + be1, Pb = x@Wb, R = x@Wn1t + bn1
    precompute_kernel<<<152, 256, DYN_PRE>>>(x, be1, bn1, N);

    // Edge phase: Q = eattr@Wc; relu(Q + Pa[row] + Pb[col]) @ We2 + be2 -> scatter
    fused_kernel<0><<<152, 256, DYN_FUSED>>>(eattr, eidx, be2, nullptr, E, E);
    // Node phase: Q = agg@Wn1b; relu(Q + R[m]) @ Wn2 + bn2 -> out
    fused_kernel<1><<<152, 256, DYN_FUSED>>>(nullptr, eidx, bn2, out, N, E);
}

// round 5
// speedup vs baseline: 6.8911x; 1.2270x over previous
#include <cuda_runtime.h>
#include <cstdint>

#define H     128
#define MAX_N 50000
#define MAX_E 800000
#define NPAD  50048

// ---------------------------------------------------------------------------
// Scratch (device globals: no allocations allowed)
// ---------------------------------------------------------------------------
__device__ float g_agg[NPAD * H];          // scatter target
__device__ float g_Pa[NPAD * H];           // x @ Wa + be1
__device__ float g_Pb[NPAD * H];           // x @ Wb
__device__ float g_R [NPAD * H];           // x @ Wn1_top + bn1
// tf32 weight images, n-major + granule swizzle for ldmatrix (4 chunks x 4096 floats)
__device__ float g_Wa[16384], g_Wb[16384], g_Wc[16384];
__device__ float g_We2img[16384];
__device__ float g_Wn1t[16384], g_Wn1b[16384], g_Wn2img[16384];
__device__ float g_zero[H];
__device__ int   g_is64;

// ---------------------------------------------------------------------------
// helpers
// ---------------------------------------------------------------------------
__device__ __forceinline__ uint32_t smem_u32(const void* p) {
    uint32_t a;
    asm("{ .reg .u64 t; cvta.to.shared.u64 t, %1; cvt.u32.u64 %0, t; }" : "=r"(a) : "l"(p));
    return a;
}
__device__ __forceinline__ void cp16(uint32_t dst, const void* src, uint32_t sz) {
    asm volatile("cp.async.ca.shared.global [%0], [%1], 16, %2;"
                 :: "r"(dst), "l"(src), "r"(sz) : "memory");
}
#define CP_COMMIT() asm volatile("cp.async.commit_group;" ::: "memory")
#define CP_WAIT(n)  asm volatile("cp.async.wait_group %0;" :: "n"(n) : "memory")

__device__ __forceinline__ uint32_t cvt_tf32(float v) {
    uint32_t r; asm("cvt.rna.tf32.f32 %0, %1;" : "=r"(r) : "f"(v)); return r;
}
__device__ __forceinline__ void mma8(float* c, const uint32_t* a, const uint32_t* b) {
    asm volatile("mma.sync.aligned.m16n8k8.row.col.f32.tf32.tf32.f32 "
        "{%0,%1,%2,%3},{%4,%5,%6,%7},{%8,%9},{%0,%1,%2,%3};"
        : "+f"(c[0]), "+f"(c[1]), "+f"(c[2]), "+f"(c[3])
        : "r"(a[0]), "r"(a[1]), "r"(a[2]), "r"(a[3]), "r"(b[0]), "r"(b[1]));
}
__device__ __forceinline__ void ldmx4(uint32_t* r, uint32_t addr) {
    asm volatile("ldmatrix.sync.aligned.m8n8.x4.shared.b16 {%0,%1,%2,%3}, [%4];"
        : "=r"(r[0]), "=r"(r[1]), "=r"(r[2]), "=r"(r[3]) : "r"(addr));
}
__device__ __forceinline__ void red2(float* p, float a, float b) {
    asm volatile("red.global.add.v2.f32 [%0], {%1, %2};" :: "l"(p), "f"(a), "f"(b) : "memory");
}

// ---------------------------------------------------------------------------
// prep kernels
// ---------------------------------------------------------------------------
__global__ void detect_idx_kernel(const unsigned int* __restrict__ e) {
    g_is64 = (e[1] == 0u && e[3] == 0u && e[5] == 0u && e[7] == 0u) ? 1 : 0;
}
__global__ void zero_agg_kernel(int off4, int n4) {
    int i = blockIdx.x * blockDim.x + threadIdx.x;
    if (i < n4) ((float4*)g_agg)[off4 + i] = make_float4(0.f, 0.f, 0.f, 0.f);
}
// n-major ldmatrix image: value W[row_off + c*32 + kk][n] stored at byte
// c*16384 + n*128 + ((kk>>2)^(n&7))*16 + (kk&3)*4, tf32(rna) pre-rounded.
__global__ void prep_all_kernel(const float* __restrict__ We1, const float* __restrict__ We2,
                                const float* __restrict__ Wn1, const float* __restrict__ Wn2) {
    int which = blockIdx.x >> 6;
    int idx = ((blockIdx.x & 63) << 8) + threadIdx.x;   // 0..16383
    const float* W; int row_off; float* img;
    switch (which) {
        case 0: W = We1; row_off =   0; img = g_Wa;     break;
        case 1: W = We1; row_off = 128; img = g_Wb;     break;
        case 2: W = We1; row_off = 256; img = g_Wc;     break;
        case 3: W = We2; row_off =   0; img = g_We2img; break;
        case 4: W = Wn1; row_off =   0; img = g_Wn1t;   break;
        case 5: W = Wn1; row_off = 128; img = g_Wn1b;   break;
        default: W = Wn2; row_off =  0; img = g_Wn2img; break;
    }
    int c = idx >> 12, rem = idx & 4095, kk = rem >> 7, n = rem & 127;
    float v = W[(size_t)(row_off + c * 32 + kk) * H + n];
    ((uint32_t*)img)[c * 4096 + n * 32 + (((kk >> 2) ^ (n & 7)) << 2) + (kk & 3)] = cvt_tf32(v);
}

// ===========================================================================
// Tile machinery: 128x128 tile, 8 warps (4M x 2N), tf32 mma.sync + ldmatrix
// A SMEM layout: row r = 128B, k-granule q stored at (q ^ (r&7))*16
// B image layout: n-major, see prep_all_kernel
// ===========================================================================
struct TileCtx {
    int lane, g, t, wM, wN, ar, halfA, l7;
    uint32_t khA, khB, aRow0, aRow1, bRow0, bRow1, bRow2, bRow3;
    __device__ __forceinline__ void init(int tid) {
        lane = tid & 31;
        int warp = tid >> 5;
        g = lane >> 2; t = lane & 3;
        wM = warp & 3; wN = warp >> 2;
        ar = tid >> 1; halfA = tid & 1;
        l7 = lane & 7;
        khA = (uint32_t)(lane >> 4);
        khB = (uint32_t)((lane >> 3) & 1);
        aRow0 = (uint32_t)((wM * 32 + ((lane >> 3) & 1) * 8 + l7) * 128);
        aRow1 = aRow0 + 16 * 128;
        uint32_t jo = (uint32_t)(lane >> 4);   // jn offset within x4 group
        bRow0 = (uint32_t)((wN * 64 + (0 + jo) * 8 + l7) * 128);
        bRow1 = (uint32_t)((wN * 64 + (2 + jo) * 8 + l7) * 128);
        bRow2 = (uint32_t)((wN * 64 + (4 + jo) * 8 + l7) * 128);
        bRow3 = (uint32_t)((wN * 64 + (6 + jo) * 8 + l7) * 128);
    }
};

template<bool DOCVT>
__device__ __forceinline__ void kstep(const TileCtx& cx, float acc[2][8][4],
                                      uint32_t Ab, uint32_t Bb, int ks) {
    uint32_t gA = (uint32_t)(((2 * ks + cx.khA) ^ cx.l7) << 4);
    uint32_t gB = (uint32_t)(((2 * ks + cx.khB) ^ cx.l7) << 4);
    uint32_t a0[4], a1[4];
    ldmx4(a0, Ab + cx.aRow0 + gA);
    ldmx4(a1, Ab + cx.aRow1 + gA);
    if (DOCVT) {
        #pragma unroll
        for (int i = 0; i < 4; i++) {
            a0[i] = cvt_tf32(__uint_as_float(a0[i]));
            a1[i] = cvt_tf32(__uint_as_float(a1[i]));
        }
    }
    uint32_t bf[16];
    ldmx4(bf + 0,  Bb + cx.bRow0 + gB);
    ldmx4(bf + 4,  Bb + cx.bRow1 + gB);
    ldmx4(bf + 8,  Bb + cx.bRow2 + gB);
    ldmx4(bf + 12, Bb + cx.bRow3 + gB);
    #pragma unroll
    for (int jn = 0; jn < 8; jn++) {
        mma8(acc[0][jn], a0, bf + 2 * jn);
        mma8(acc[1][jn], a1, bf + 2 * jn);
    }
}

// ---------------------------------------------------------------------------
// Precompute GEMM: Pa = x@Wa + be1, Pb = x@Wb, R = x@Wn1t + bn1
// smem: A dbuf 2x4096 | B dbuf 2x4096 = 64KB
// ---------------------------------------------------------------------------
__global__ void __launch_bounds__(256, 1)
precompute_kernel(const float* __restrict__ x, const float* __restrict__ be1,
                  const float* __restrict__ bn1, int M)
{
    extern __shared__ __align__(16) float sm[];
    __shared__ float sB[128];
    const int tid = threadIdx.x;
    TileCtx cx; cx.init(tid);
    const uint32_t aBufU = smem_u32(sm);
    const uint32_t bBufU = smem_u32(sm + 8192);

    const int T = (M + 127) >> 7;
    for (int v = blockIdx.x; v < 3 * T; v += gridDim.x) {
        const int which = v / T;
        const int mbase = (v % T) << 7;
        __syncthreads();
        const float* W1img = (which == 0) ? g_Wa : (which == 1) ? g_Wb : g_Wn1t;
        const float* bias  = (which == 0) ? be1 : (which == 1) ? g_zero : bn1;
        float* outp        = (which == 0) ? g_Pa : (which == 1) ? g_Pb : g_R;
        if (tid < 128) sB[tid] = bias[tid];

        auto stage = [&](int c) {
            bool valid = (mbase + cx.ar) < M;
            const float* srcA = x + (size_t)(valid ? (mbase + cx.ar) : 0) * H
                              + (c << 5) + cx.halfA * 16;
            uint32_t dstA = aBufU + (uint32_t)((c & 1) * 16384 + cx.ar * 128);
            uint32_t sz = valid ? 16u : 0u;
            #pragma unroll
            for (int i = 0; i < 4; i++) {
                int q = cx.halfA * 4 + i, qs = q ^ (cx.ar & 7);
                cp16(dstA + qs * 16, srcA + i * 4, sz);
            }
            const float4* srcB = (const float4*)(W1img + c * 4096) + tid;
            uint32_t dstB = bBufU + (uint32_t)((c & 1) * 16384) + (uint32_t)tid * 16;
            #pragma unroll
            for (int i = 0; i < 4; i++) cp16(dstB + i * 4096, srcB + i * 256, 16);
            CP_COMMIT();
        };

        float acc[2][8][4];
        #pragma unroll
        for (int mt = 0; mt < 2; mt++)
            #pragma unroll
            for (int jn = 0; jn < 8; jn++)
                #pragma unroll
                for (int i = 0; i < 4; i++) acc[mt][jn][i] = 0.f;

        stage(0); stage(1);
        #pragma unroll
        for (int c = 0; c < 4; c++) {
            if (c < 3) { CP_WAIT(1); } else { CP_WAIT(0); }
            __syncthreads();
            uint32_t Ab = aBufU + (uint32_t)((c & 1) * 16384);
            uint32_t Bb = bBufU + (uint32_t)((c & 1) * 16384);
            #pragma unroll
            for (int ks = 0; ks < 4; ks++) kstep<true>(cx, acc, Ab, Bb, ks);
            __syncthreads();
            if (c + 2 < 4) stage(c + 2);
        }

        // direct v2 stores
        #pragma unroll
        for (int mt = 0; mt < 2; mt++) {
            const int r0r = cx.wM * 32 + cx.g + mt * 16, r8r = r0r + 8;
            #pragma unroll
            for (int jn = 0; jn < 8; jn++) {
                int col0 = cx.wN * 64 + jn * 8 + 2 * cx.t;
                float b0 = sB[col0], b1 = sB[col0 + 1];
                if (mbase + r0r < M)
                    *(float2*)(outp + (size_t)(mbase + r0r) * H + col0) =
                        make_float2(acc[mt][jn][0] + b0, acc[mt][jn][1] + b1);
                if (mbase + r8r < M)
                    *(float2*)(outp + (size_t)(mbase + r8r) * H + col0) =
                        make_float2(acc[mt][jn][2] + b0, acc[mt][jn][3] + b1);
            }
        }
    }
}

// ---------------------------------------------------------------------------
// Fused phase kernel (persistent weights in SMEM).
// MODE 0 (edge): Q = eattr@Wc; hid = relu(Q + Pa[row] + Pb[col]);
//                msg = hid@We2 + be2; red.v2 scatter into g_agg[col]
// MODE 1 (node): Q = agg@Wn1b; hid = relu(Q + R[m]); out = hid@Wn2 + bn2
// smem floats: A dbuf 8192 | sW1 16384 | sW2 16384 | sHid 16384 = 57344 (224KB)
// ---------------------------------------------------------------------------
template<int MODE>
__global__ void __launch_bounds__(256, 1)
fused_kernel(const float* __restrict__ eattr, const void* __restrict__ eidx,
             const float* __restrict__ b2v, float* __restrict__ outp,
             int M, int E)
{
    extern __shared__ __align__(16) float sm[];
    float* const sW1  = sm + 8192;
    float* const sW2  = sm + 24576;
    float* const sHid = sm + 40960;
    __shared__ int   sRow[128], sCol[128];
    __shared__ float sB2[128];

    const int tid = threadIdx.x;
    TileCtx cx; cx.init(tid);
    const uint32_t aBufU = smem_u32(sm);
    const uint32_t w1U   = smem_u32(sW1);
    const uint32_t w2U   = smem_u32(sW2);
    const uint32_t hidU  = smem_u32(sHid);

    { // persistent weight images
        const float4* s1 = (const float4*)((MODE == 0) ? g_Wc : g_Wn1b);
        const float4* s2 = (const float4*)((MODE == 0) ? g_We2img : g_Wn2img);
        float4* d1 = (float4*)sW1; float4* d2 = (float4*)sW2;
        #pragma unroll
        for (int i = 0; i < 16; i++) { d1[tid + i * 256] = s1[tid + i * 256];
                                       d2[tid + i * 256] = s2[tid + i * 256]; }
    }
    if (tid < 128) sB2[tid] = b2v[tid];
    const int is64v = g_is64;
    const float* Asrc = (MODE == 0) ? eattr : g_agg;
    __syncthreads();

    const int ntiles = (M + 127) >> 7;
    for (int tile = blockIdx.x; tile < ntiles; tile += gridDim.x) {
        const int mbase = tile << 7;
        __syncthreads();                 // prev-tile scatter readers of sCol done
        if (MODE == 0 && tid < 128) {
            int e = mbase + tid; int rI = 0, cI = 0;
            if (e < M) {
                if (is64v) {
                    const long long* p = (const long long*)eidx;
                    rI = (int)p[e]; cI = (int)p[(long long)E + e];
                } else {
                    const int* p = (const int*)eidx;
                    rI = p[e]; cI = p[E + e];
                }
            }
            sRow[tid] = rI; sCol[tid] = cI;
        }
        __syncthreads();

        auto stage = [&](int c) {
            bool valid = (mbase + cx.ar) < M;
            const float* srcA = Asrc + (size_t)(valid ? (mbase + cx.ar) : 0) * H
                              + (c << 5) + cx.halfA * 16;
            uint32_t dstA = aBufU + (uint32_t)((c & 1) * 16384 + cx.ar * 128);
            uint32_t sz = valid ? 16u : 0u;
            #pragma unroll
            for (int i = 0; i < 4; i++) {
                int q = cx.halfA * 4 + i, qs = q ^ (cx.ar & 7);
                cp16(dstA + qs * 16, srcA + i * 4, sz);
            }
            CP_COMMIT();
        };

        float acc[2][8][4];
        #pragma unroll
        for (int mt = 0; mt < 2; mt++)
            #pragma unroll
            for (int jn = 0; jn < 8; jn++)
                #pragma unroll
                for (int i = 0; i < 4; i++) acc[mt][jn][i] = 0.f;

        stage(0); stage(1);
        // ---------------- L1: Q GEMM, K=128, weights persistent -------------
        #pragma unroll
        for (int c = 0; c < 4; c++) {
            if (c < 3) { CP_WAIT(1); } else { CP_WAIT(0); }
            __syncthreads();
            uint32_t Ab = aBufU + (uint32_t)((c & 1) * 16384);
            uint32_t Bb = w1U + (uint32_t)(c * 16384);
            #pragma unroll
            for (int ks = 0; ks < 4; ks++) kstep<true>(cx, acc, Ab, Bb, ks);
            __syncthreads();
            if (c + 2 < 4) stage(c + 2);
        }

        // -------- add gathered per-node terms, relu -> sHid (tf32) ----------
        const int axor = cx.g << 2;
        #pragma unroll
        for (int mt = 0; mt < 2; mt++) {
            const int r0r = cx.wM * 32 + cx.g + mt * 16, r8r = r0r + 8;
            int ia0, ia8, ic0 = 0, ic8 = 0;
            if (MODE == 0) {
                ia0 = sRow[r0r]; ic0 = sCol[r0r];
                ia8 = sRow[r8r]; ic8 = sCol[r8r];
            } else {
                ia0 = min(mbase + r0r, M - 1);
                ia8 = min(mbase + r8r, M - 1);
            }
            const float* PaB = (MODE == 0) ? g_Pa : g_R;
            #pragma unroll
            for (int jn = 0; jn < 8; jn++) {
                int col0 = cx.wN * 64 + jn * 8 + 2 * cx.t;
                float2 pa0 = *(const float2*)(PaB + (size_t)ia0 * H + col0);
                float2 pa8 = *(const float2*)(PaB + (size_t)ia8 * H + col0);
                float v0 = acc[mt][jn][0] + pa0.x, v1 = acc[mt][jn][1] + pa0.y;
                float v2 = acc[mt][jn][2] + pa8.x, v3 = acc[mt][jn][3] + pa8.y;
                if (MODE == 0) {
                    float2 pb0 = *(const float2*)(g_Pb + (size_t)ic0 * H + col0);
                    float2 pb8 = *(const float2*)(g_Pb + (size_t)ic8 * H + col0);
                    v0 += pb0.x; v1 += pb0.y; v2 += pb8.x; v3 += pb8.y;
                }
                uint32_t u0 = cvt_tf32(fmaxf(v0, 0.f));
                uint32_t u1 = cvt_tf32(fmaxf(v1, 0.f));
                uint32_t u2 = cvt_tf32(fmaxf(v2, 0.f));
                uint32_t u3 = cvt_tf32(fmaxf(v3, 0.f));
                int slab = col0 >> 5, kk = col0 & 31;
                uint32_t* dst = (uint32_t*)(sHid + slab * 4096);
                *(uint2*)(dst + r0r * 32 + (kk ^ axor)) = make_uint2(u0, u1);
                *(uint2*)(dst + r8r * 32 + (kk ^ axor)) = make_uint2(u2, u3);
                acc[mt][jn][0] = acc[mt][jn][1] = acc[mt][jn][2] = acc[mt][jn][3] = 0.f;
            }
        }
        __syncthreads();

        // ------------------------- L2 (K=128) ------------------------------
        #pragma unroll
        for (int ks16 = 0; ks16 < 16; ks16++)
            kstep<false>(cx, acc,
                         hidU + (uint32_t)((ks16 >> 2) * 16384),
                         w2U  + (uint32_t)((ks16 >> 2) * 16384), ks16 & 3);

        // ------------- direct epilogue: bias2 + scatter/store --------------
        #pragma unroll
        for (int mt = 0; mt < 2; mt++) {
            const int r0r = cx.wM * 32 + cx.g + mt * 16, r8r = r0r + 8;
            #pragma unroll
            for (int jn = 0; jn < 8; jn++) {
                int col0 = cx.wN * 64 + jn * 8 + 2 * cx.t;
                float b0 = sB2[col0], b1 = sB2[col0 + 1];
                float v0 = acc[mt][jn][0] + b0, v1 = acc[mt][jn][1] + b1;
                float v2 = acc[mt][jn][2] + b0, v3 = acc[mt][jn][3] + b1;
                if (MODE == 0) {
                    red2(g_agg + (size_t)sCol[r0r] * H + col0, v0, v1);
                    red2(g_agg + (size_t)sCol[r8r] * H + col0, v2, v3);
                } else {
                    if (mbase + r0r < M)
                        *(float2*)(outp + (size_t)(mbase + r0r) * H + col0) = make_float2(v0, v1);
                    if (mbase + r8r < M)
                        *(float2*)(outp + (size_t)(mbase + r8r) * H + col0) = make_float2(v2, v3);
                }
            }
        }
    }
}

// ---------------------------------------------------------------------------
#define DYN_FUSED (57344 * 4)   // 229376 B
#define DYN_PRE   (16384 * 4)   // 65536 B

extern "C" void kernel_launch(void* const* d_in, const int* in_sizes, int n_in,
                              void* d_out, int out_size) {
    const float* x     = (const float*)d_in[0];
    const void*  eidx  = d_in[1];
    const float* eattr = (const float*)d_in[2];
    const float* We1   = (const float*)d_in[3];
    const float* be1   = (const float*)d_in[4];
    const float* We2   = (const float*)d_in[5];
    const float* be2   = (const float*)d_in[6];
    const float* Wn1   = (const float*)d_in[7];
    const float* bn1   = (const float*)d_in[8];
    const float* Wn2   = (const float*)d_in[9];
    const float* bn2   = (const float*)d_in[10];
    float* out = (float*)d_out;

    const int N = in_sizes[0] / H;
    const int E = in_sizes[1] / 2;

    cudaFuncSetAttribute(fused_kernel<0>, cudaFuncAttributeMaxDynamicSharedMemorySize, DYN_FUSED);
    cudaFuncSetAttribute(fused_kernel<1>, cudaFuncAttributeMaxDynamicSharedMemorySize, DYN_FUSED);
    cudaFuncSetAttribute(precompute_kernel, cudaFuncAttributeMaxDynamicSharedMemorySize, DYN_PRE);

    // Launch order fixed so ncu (-s 5 -c 1) profiles fused_kernel<0> (edge phase):
    // 1:detect 2:prep 3:zeroA 4:zeroB 5:precompute 6:fused<0> 7:fused<1>
    detect_idx_kernel<<<1, 1>>>((const unsigned int*)eidx);
    prep_all_kernel<<<448, 256>>>(We1, We2, Wn1, Wn2);

    const int n4 = N * H / 4;
    const int h4 = n4 / 2;
    zero_agg_kernel<<<(h4 + 255) / 256, 256>>>(0, h4);
    zero_agg_kernel<<<(n4 - h4 + 255) / 256, 256>>>(h4, n4 - h4);

    precompute_kernel<<<304, 256, DYN_PRE>>>(x, be1, bn1, N);

    fused_kernel<0><<<152, 256, DYN_FUSED>>>(eattr, eidx, be2, nullptr, E, E);
    fused_kernel<1><<<152, 256, DYN_FUSED>>>(nullptr, eidx, bn2, out, N, E);
}

// round 6
// speedup vs baseline: 9.9716x; 1.4470x over previous
#include <cuda_runtime.h>
#include <cstdint>

#define H     128
#define MAX_N 50000
#define MAX_E 800000
#define NPAD  50048

// ---------------------------------------------------------------------------
// Scratch (device globals: no allocations allowed)
// ---------------------------------------------------------------------------
__device__ float g_agg[NPAD * H];          // Hsum during edge phase, then agg (in-place)
__device__ float g_deg[NPAD];              // per-node in-degree (float)
__device__ float g_Pa[NPAD * H];           // x @ Wa + be1
__device__ float g_Pb[NPAD * H];           // x @ Wb
__device__ float g_R [NPAD * H];           // x @ Wn1_top + bn1
// tf32 weight images, n-major + granule swizzle for ldmatrix (4 chunks x 4096 floats)
__device__ float g_Wa[16384], g_Wb[16384], g_Wc[16384];
__device__ float g_We2img[16384];
__device__ float g_Wn1t[16384], g_Wn1b[16384], g_Wn2img[16384];
__device__ float g_zero[H];
__device__ int   g_is64;

// ---------------------------------------------------------------------------
// helpers
// ---------------------------------------------------------------------------
__device__ __forceinline__ uint32_t smem_u32(const void* p) {
    uint32_t a;
    asm("{ .reg .u64 t; cvta.to.shared.u64 t, %1; cvt.u32.u64 %0, t; }" : "=r"(a) : "l"(p));
    return a;
}
__device__ __forceinline__ void cp16(uint32_t dst, const void* src, uint32_t sz) {
    asm volatile("cp.async.ca.shared.global [%0], [%1], 16, %2;"
                 :: "r"(dst), "l"(src), "r"(sz) : "memory");
}
#define CP_COMMIT() asm volatile("cp.async.commit_group;" ::: "memory")
#define CP_WAIT(n)  asm volatile("cp.async.wait_group %0;" :: "n"(n) : "memory")

__device__ __forceinline__ uint32_t cvt_tf32(float v) {
    uint32_t r; asm("cvt.rna.tf32.f32 %0, %1;" : "=r"(r) : "f"(v)); return r;
}
__device__ __forceinline__ void mma8(float* c, const uint32_t* a, const uint32_t* b) {
    asm volatile("mma.sync.aligned.m16n8k8.row.col.f32.tf32.tf32.f32 "
        "{%0,%1,%2,%3},{%4,%5,%6,%7},{%8,%9},{%0,%1,%2,%3};"
        : "+f"(c[0]), "+f"(c[1]), "+f"(c[2]), "+f"(c[3])
        : "r"(a[0]), "r"(a[1]), "r"(a[2]), "r"(a[3]), "r"(b[0]), "r"(b[1]));
}
__device__ __forceinline__ void ldmx4(uint32_t* r, uint32_t addr) {
    asm volatile("ldmatrix.sync.aligned.m8n8.x4.shared.b16 {%0,%1,%2,%3}, [%4];"
        : "=r"(r[0]), "=r"(r[1]), "=r"(r[2]), "=r"(r[3]) : "r"(addr));
}
__device__ __forceinline__ void red2(float* p, float a, float b) {
    asm volatile("red.global.add.v2.f32 [%0], {%1, %2};" :: "l"(p), "f"(a), "f"(b) : "memory");
}
__device__ __forceinline__ void red1(float* p, float a) {
    asm volatile("red.global.add.f32 [%0], %1;" :: "l"(p), "f"(a) : "memory");
}

// ---------------------------------------------------------------------------
// prep kernels
// ---------------------------------------------------------------------------
__global__ void zero_kernel(int n4, int nd4) {
    int i = blockIdx.x * blockDim.x + threadIdx.x;
    if (i < n4) ((float4*)g_agg)[i] = make_float4(0.f, 0.f, 0.f, 0.f);
    if (i < nd4) ((float4*)g_deg)[i] = make_float4(0.f, 0.f, 0.f, 0.f);
}
__global__ void detect_idx_kernel(const unsigned int* __restrict__ e) {
    g_is64 = (e[1] == 0u && e[3] == 0u && e[5] == 0u && e[7] == 0u) ? 1 : 0;
}
// n-major ldmatrix image: value W[row_off + c*32 + kk][n] stored at byte
// c*16384 + n*128 + ((kk>>2)^(n&7))*16 + (kk&3)*4, tf32(rna) pre-rounded.
__global__ void prep_all_kernel(const float* __restrict__ We1, const float* __restrict__ We2,
                                const float* __restrict__ Wn1, const float* __restrict__ Wn2) {
    int which = blockIdx.x >> 6;
    int idx = ((blockIdx.x & 63) << 8) + threadIdx.x;   // 0..16383
    const float* W; int row_off; float* img;
    switch (which) {
        case 0: W = We1; row_off =   0; img = g_Wa;     break;
        case 1: W = We1; row_off = 128; img = g_Wb;     break;
        case 2: W = We1; row_off = 256; img = g_Wc;     break;
        case 3: W = We2; row_off =   0; img = g_We2img; break;
        case 4: W = Wn1; row_off =   0; img = g_Wn1t;   break;
        case 5: W = Wn1; row_off = 128; img = g_Wn1b;   break;
        default: W = Wn2; row_off =  0; img = g_Wn2img; break;
    }
    int c = idx >> 12, rem = idx & 4095, kk = rem >> 7, n = rem & 127;
    float v = W[(size_t)(row_off + c * 32 + kk) * H + n];
    ((uint32_t*)img)[c * 4096 + n * 32 + (((kk >> 2) ^ (n & 7)) << 2) + (kk & 3)] = cvt_tf32(v);
}

// ===========================================================================
// Tile machinery: 128x128 tile, 8 warps (4M x 2N), tf32 mma.sync + ldmatrix
// A SMEM layout: row r = 128B, k-granule q stored at (q ^ (r&7))*16
// B image layout: n-major, see prep_all_kernel
// ===========================================================================
struct TileCtx {
    int lane, g, t, wM, wN, ar, halfA, l7;
    uint32_t khA, khB, aRow0, aRow1, bRow0, bRow1, bRow2, bRow3;
    __device__ __forceinline__ void init(int tid) {
        lane = tid & 31;
        int warp = tid >> 5;
        g = lane >> 2; t = lane & 3;
        wM = warp & 3; wN = warp >> 2;
        ar = tid >> 1; halfA = tid & 1;
        l7 = lane & 7;
        khA = (uint32_t)(lane >> 4);
        khB = (uint32_t)((lane >> 3) & 1);
        aRow0 = (uint32_t)((wM * 32 + ((lane >> 3) & 1) * 8 + l7) * 128);
        aRow1 = aRow0 + 16 * 128;
        uint32_t jo = (uint32_t)(lane >> 4);
        bRow0 = (uint32_t)((wN * 64 + (0 + jo) * 8 + l7) * 128);
        bRow1 = (uint32_t)((wN * 64 + (2 + jo) * 8 + l7) * 128);
        bRow2 = (uint32_t)((wN * 64 + (4 + jo) * 8 + l7) * 128);
        bRow3 = (uint32_t)((wN * 64 + (6 + jo) * 8 + l7) * 128);
    }
};

template<bool DOCVT>
__device__ __forceinline__ void kstep(const TileCtx& cx, float acc[2][8][4],
                                      uint32_t Ab, uint32_t Bb, int ks) {
    uint32_t gA = (uint32_t)(((2 * ks + cx.khA) ^ cx.l7) << 4);
    uint32_t gB = (uint32_t)(((2 * ks + cx.khB) ^ cx.l7) << 4);
    uint32_t a0[4], a1[4];
    ldmx4(a0, Ab + cx.aRow0 + gA);
    ldmx4(a1, Ab + cx.aRow1 + gA);
    if (DOCVT) {
        #pragma unroll
        for (int i = 0; i < 4; i++) {
            a0[i] = cvt_tf32(__uint_as_float(a0[i]));
            a1[i] = cvt_tf32(__uint_as_float(a1[i]));
        }
    }
    uint32_t bf[16];
    ldmx4(bf + 0,  Bb + cx.bRow0 + gB);
    ldmx4(bf + 4,  Bb + cx.bRow1 + gB);
    ldmx4(bf + 8,  Bb + cx.bRow2 + gB);
    ldmx4(bf + 12, Bb + cx.bRow3 + gB);
    #pragma unroll
    for (int jn = 0; jn < 8; jn++) {
        mma8(acc[0][jn], a0, bf + 2 * jn);
        mma8(acc[1][jn], a1, bf + 2 * jn);
    }
}

// ---------------------------------------------------------------------------
// Generic GEMM: outp = srcA @ Wimg + scale*bias   (scale = deg[row] or 1)
// smem: A dbuf 2x4096 | B dbuf 2x4096 = 64KB
// ---------------------------------------------------------------------------
__global__ void __launch_bounds__(256, 2)
gemm_kernel(const float* __restrict__ srcA, const float* __restrict__ Wimg,
            const float* __restrict__ bias, const float* __restrict__ degv,
            float* __restrict__ outp, int M)
{
    extern __shared__ __align__(16) float sm[];
    __shared__ float sB[128];
    const int tid = threadIdx.x;
    TileCtx cx; cx.init(tid);
    const uint32_t aBufU = smem_u32(sm);
    const uint32_t bBufU = smem_u32(sm + 8192);
    if (tid < 128) sB[tid] = bias[tid];

    const int T = (M + 127) >> 7;
    for (int tile = blockIdx.x; tile < T; tile += gridDim.x) {
        const int mbase = tile << 7;
        __syncthreads();

        auto stage = [&](int c) {
            bool valid = (mbase + cx.ar) < M;
            const float* srcAr = srcA + (size_t)(valid ? (mbase + cx.ar) : 0) * H
                               + (c << 5) + cx.halfA * 16;
            uint32_t dstA = aBufU + (uint32_t)((c & 1) * 16384 + cx.ar * 128);
            uint32_t sz = valid ? 16u : 0u;
            #pragma unroll
            for (int i = 0; i < 4; i++) {
                int q = cx.halfA * 4 + i, qs = q ^ (cx.ar & 7);
                cp16(dstA + qs * 16, srcAr + i * 4, sz);
            }
            const float4* srcB = (const float4*)(Wimg + c * 4096) + tid;
            uint32_t dstB = bBufU + (uint32_t)((c & 1) * 16384) + (uint32_t)tid * 16;
            #pragma unroll
            for (int i = 0; i < 4; i++) cp16(dstB + i * 4096, srcB + i * 256, 16);
            CP_COMMIT();
        };

        float acc[2][8][4];
        #pragma unroll
        for (int mt = 0; mt < 2; mt++)
            #pragma unroll
            for (int jn = 0; jn < 8; jn++)
                #pragma unroll
                for (int i = 0; i < 4; i++) acc[mt][jn][i] = 0.f;

        stage(0); stage(1);
        #pragma unroll
        for (int c = 0; c < 4; c++) {
            if (c < 3) { CP_WAIT(1); } else { CP_WAIT(0); }
            __syncthreads();
            uint32_t Ab = aBufU + (uint32_t)((c & 1) * 16384);
            uint32_t Bb = bBufU + (uint32_t)((c & 1) * 16384);
            #pragma unroll
            for (int ks = 0; ks < 4; ks++) kstep<true>(cx, acc, Ab, Bb, ks);
            __syncthreads();
            if (c + 2 < 4) stage(c + 2);
        }

        #pragma unroll
        for (int mt = 0; mt < 2; mt++) {
            const int r0r = cx.wM * 32 + cx.g + mt * 16, r8r = r0r + 8;
            float s0 = 1.f, s8 = 1.f;
            if (degv) {
                s0 = (mbase + r0r < M) ? degv[mbase + r0r] : 0.f;
                s8 = (mbase + r8r < M) ? degv[mbase + r8r] : 0.f;
            }
            #pragma unroll
            for (int jn = 0; jn < 8; jn++) {
                int col0 = cx.wN * 64 + jn * 8 + 2 * cx.t;
                float b0 = sB[col0], b1 = sB[col0 + 1];
                if (mbase + r0r < M)
                    *(float2*)(outp + (size_t)(mbase + r0r) * H + col0) =
                        make_float2(acc[mt][jn][0] + s0 * b0, acc[mt][jn][1] + s0 * b1);
                if (mbase + r8r < M)
                    *(float2*)(outp + (size_t)(mbase + r8r) * H + col0) =
                        make_float2(acc[mt][jn][2] + s8 * b0, acc[mt][jn][3] + s8 * b1);
            }
        }
    }
}

// ---------------------------------------------------------------------------
// Edge kernel: Q = eattr@Wc (Wc persistent in SMEM);
// hid = relu(Q + Pa[row] + Pb[col]); red.v2 hid into g_agg[col] (as Hsum);
// deg[col] += 1.
// smem floats: A dbuf 8192 | sW1 16384 = 24576 (96KB) -> 2 CTAs/SM
// ---------------------------------------------------------------------------
__global__ void __launch_bounds__(256, 2)
edge_kernel(const float* __restrict__ eattr, const void* __restrict__ eidx, int M)
{
    extern __shared__ __align__(16) float sm[];
    float* const sW1 = sm + 8192;
    __shared__ int sRow[128], sCol[128];

    const int tid = threadIdx.x;
    TileCtx cx; cx.init(tid);
    const uint32_t aBufU = smem_u32(sm);
    const uint32_t w1U   = smem_u32(sW1);

    { // persistent Wc image
        const float4* s1 = (const float4*)g_Wc;
        float4* d1 = (float4*)sW1;
        #pragma unroll
        for (int i = 0; i < 16; i++) d1[tid + i * 256] = s1[tid + i * 256];
    }
    const int is64v = g_is64;
    __syncthreads();

    const int ntiles = (M + 127) >> 7;
    for (int tile = blockIdx.x; tile < ntiles; tile += gridDim.x) {
        const int mbase = tile << 7;
        __syncthreads();                 // prev-tile epilogue readers of sCol done
        if (tid < 128) {
            int e = mbase + tid; int rI = 0, cI = 0;
            if (e < M) {
                if (is64v) {
                    const long long* p = (const long long*)eidx;
                    rI = (int)p[e]; cI = (int)p[(long long)M + e];
                } else {
                    const int* p = (const int*)eidx;
                    rI = p[e]; cI = p[M + e];
                }
            }
            sRow[tid] = rI; sCol[tid] = cI;
        }
        __syncthreads();

        auto stage = [&](int c) {
            bool valid = (mbase + cx.ar) < M;
            const float* srcA = eattr + (size_t)(valid ? (mbase + cx.ar) : 0) * H
                              + (c << 5) + cx.halfA * 16;
            uint32_t dstA = aBufU + (uint32_t)((c & 1) * 16384 + cx.ar * 128);
            uint32_t sz = valid ? 16u : 0u;
            #pragma unroll
            for (int i = 0; i < 4; i++) {
                int q = cx.halfA * 4 + i, qs = q ^ (cx.ar & 7);
                cp16(dstA + qs * 16, srcA + i * 4, sz);
            }
            CP_COMMIT();
        };

        float acc[2][8][4];
        #pragma unroll
        for (int mt = 0; mt < 2; mt++)
            #pragma unroll
            for (int jn = 0; jn < 8; jn++)
                #pragma unroll
                for (int i = 0; i < 4; i++) acc[mt][jn][i] = 0.f;

        stage(0); stage(1);
        #pragma unroll
        for (int c = 0; c < 4; c++) {
            if (c < 3) { CP_WAIT(1); } else { CP_WAIT(0); }
            __syncthreads();
            uint32_t Ab = aBufU + (uint32_t)((c & 1) * 16384);
            uint32_t Bb = w1U + (uint32_t)(c * 16384);
            #pragma unroll
            for (int ks = 0; ks < 4; ks++) kstep<true>(cx, acc, Ab, Bb, ks);
            __syncthreads();
            if (c + 2 < 4) stage(c + 2);
        }

        // ---- epilogue: hid = relu(acc + Pa[row] + Pb[col]) -> scatter ------
        #pragma unroll
        for (int mt = 0; mt < 2; mt++) {
            const int r0r = cx.wM * 32 + cx.g + mt * 16, r8r = r0r + 8;
            const bool v0r = (mbase + r0r) < M, v8r = (mbase + r8r) < M;
            const int ia0 = sRow[r0r], ic0 = sCol[r0r];
            const int ia8 = sRow[r8r], ic8 = sCol[r8r];
            const float* pa0 = g_Pa + (size_t)ia0 * H;
            const float* pa8 = g_Pa + (size_t)ia8 * H;
            const float* pb0 = g_Pb + (size_t)ic0 * H;
            const float* pb8 = g_Pb + (size_t)ic8 * H;
            float* h0 = g_agg + (size_t)ic0 * H;
            float* h8 = g_agg + (size_t)ic8 * H;
            if (cx.wN == 0 && cx.t == 0) {
                if (v0r) red1(g_deg + ic0, 1.f);
                if (v8r) red1(g_deg + ic8, 1.f);
            }
            #pragma unroll
            for (int jn = 0; jn < 8; jn++) {
                int col0 = cx.wN * 64 + jn * 8 + 2 * cx.t;
                if (v0r) {
                    float2 a = *(const float2*)(pa0 + col0);
                    float2 b = *(const float2*)(pb0 + col0);
                    red2(h0 + col0, fmaxf(acc[mt][jn][0] + a.x + b.x, 0.f),
                                    fmaxf(acc[mt][jn][1] + a.y + b.y, 0.f));
                }
                if (v8r) {
                    float2 a = *(const float2*)(pa8 + col0);
                    float2 b = *(const float2*)(pb8 + col0);
                    red2(h8 + col0, fmaxf(acc[mt][jn][2] + a.x + b.x, 0.f),
                                    fmaxf(acc[mt][jn][3] + a.y + b.y, 0.f));
                }
            }
        }
    }
}

// ---------------------------------------------------------------------------
// Node kernel: Q = agg@Wn1b; hid = relu(Q + R[m]); out = hid@Wn2 + bn2
// smem floats: A dbuf 8192 | sW1 16384 | sW2 16384 | sHid 16384 = 57344 (224KB)
// ---------------------------------------------------------------------------
__global__ void __launch_bounds__(256, 1)
node_kernel(const float* __restrict__ b2v, float* __restrict__ outp, int M)
{
    extern __shared__ __align__(16) float sm[];
    float* const sW1  = sm + 8192;
    float* const sW2  = sm + 24576;
    float* const sHid = sm + 40960;
    __shared__ float sB2[128];

    const int tid = threadIdx.x;
    TileCtx cx; cx.init(tid);
    const uint32_t aBufU = smem_u32(sm);
    const uint32_t w1U   = smem_u32(sW1);
    const uint32_t w2U   = smem_u32(sW2);
    const uint32_t hidU  = smem_u32(sHid);

    {
        const float4* s1 = (const float4*)g_Wn1b;
        const float4* s2 = (const float4*)g_Wn2img;
        float4* d1 = (float4*)sW1; float4* d2 = (float4*)sW2;
        #pragma unroll
        for (int i = 0; i < 16; i++) { d1[tid + i * 256] = s1[tid + i * 256];
                                       d2[tid + i * 256] = s2[tid + i * 256]; }
    }
    if (tid < 128) sB2[tid] = b2v[tid];
    __syncthreads();

    const int ntiles = (M + 127) >> 7;
    for (int tile = blockIdx.x; tile < ntiles; tile += gridDim.x) {
        const int mbase = tile << 7;
        __syncthreads();

        auto stage = [&](int c) {
            bool valid = (mbase + cx.ar) < M;
            const float* srcA = g_agg + (size_t)(valid ? (mbase + cx.ar) : 0) * H
                              + (c << 5) + cx.halfA * 16;
            uint32_t dstA = aBufU + (uint32_t)((c & 1) * 16384 + cx.ar * 128);
            uint32_t sz = valid ? 16u : 0u;
            #pragma unroll
            for (int i = 0; i < 4; i++) {
                int q = cx.halfA * 4 + i, qs = q ^ (cx.ar & 7);
                cp16(dstA + qs * 16, srcA + i * 4, sz);
            }
            CP_COMMIT();
        };

        float acc[2][8][4];
        #pragma unroll
        for (int mt = 0; mt < 2; mt++)
            #pragma unroll
            for (int jn = 0; jn < 8; jn++)
                #pragma unroll
                for (int i = 0; i < 4; i++) acc[mt][jn][i] = 0.f;

        stage(0); stage(1);
        #pragma unroll
        for (int c = 0; c < 4; c++) {
            if (c < 3) { CP_WAIT(1); } else { CP_WAIT(0); }
            __syncthreads();
            uint32_t Ab = aBufU + (uint32_t)((c & 1) * 16384);
            uint32_t Bb = w1U + (uint32_t)(c * 16384);
            #pragma unroll
            for (int ks = 0; ks < 4; ks++) kstep<true>(cx, acc, Ab, Bb, ks);
            __syncthreads();
            if (c + 2 < 4) stage(c + 2);
        }

        // hid = relu(acc + R[m]) -> sHid (tf32, A layout)
        const int axor = cx.g << 2;
        #pragma unroll
        for (int mt = 0; mt < 2; mt++) {
            const int r0r = cx.wM * 32 + cx.g + mt * 16, r8r = r0r + 8;
            const int ia0 = min(mbase + r0r, M - 1);
            const int ia8 = min(mbase + r8r, M - 1);
            #pragma unroll
            for (int jn = 0; jn < 8; jn++) {
                int col0 = cx.wN * 64 + jn * 8 + 2 * cx.t;
                float2 ra = *(const float2*)(g_R + (size_t)ia0 * H + col0);
                float2 rb = *(const float2*)(g_R + (size_t)ia8 * H + col0);
                uint32_t u0 = cvt_tf32(fmaxf(acc[mt][jn][0] + ra.x, 0.f));
                uint32_t u1 = cvt_tf32(fmaxf(acc[mt][jn][1] + ra.y, 0.f));
                uint32_t u2 = cvt_tf32(fmaxf(acc[mt][jn][2] + rb.x, 0.f));
                uint32_t u3 = cvt_tf32(fmaxf(acc[mt][jn][3] + rb.y, 0.f));
                int slab = col0 >> 5, kk = col0 & 31;
                uint32_t* dst = (uint32_t*)(sHid + slab * 4096);
                *(uint2*)(dst + r0r * 32 + (kk ^ axor)) = make_uint2(u0, u1);
                *(uint2*)(dst + r8r * 32 + (kk ^ axor)) = make_uint2(u2, u3);
                acc[mt][jn][0] = acc[mt][jn][1] = acc[mt][jn][2] = acc[mt][jn][3] = 0.f;
            }
        }
        __syncthreads();

        #pragma unroll
        for (int ks16 = 0; ks16 < 16; ks16++)
            kstep<false>(cx, acc,
                         hidU + (uint32_t)((ks16 >> 2) * 16384),
                         w2U  + (uint32_t)((ks16 >> 2) * 16384), ks16 & 3);

        #pragma unroll
        for (int mt = 0; mt < 2; mt++) {
            const int r0r = cx.wM * 32 + cx.g + mt * 16, r8r = r0r + 8;
            #pragma unroll
            for (int jn = 0; jn < 8; jn++) {
                int col0 = cx.wN * 64 + jn * 8 + 2 * cx.t;
                float b0 = sB2[col0], b1 = sB2[col0 + 1];
                if (mbase + r0r < M)
                    *(float2*)(outp + (size_t)(mbase + r0r) * H + col0) =
                        make_float2(acc[mt][jn][0] + b0, acc[mt][jn][1] + b1);
                if (mbase + r8r < M)
                    *(float2*)(outp + (size_t)(mbase + r8r) * H + col0) =
                        make_float2(acc[mt][jn][2] + b0, acc[mt][jn][3] + b1);
            }
        }
    }
}

// ---------------------------------------------------------------------------
#define DYN_GEMM (16384 * 4)   //  64KB
#define DYN_EDGE (24576 * 4)   //  96KB
#define DYN_NODE (57344 * 4)   // 224KB

extern "C" void kernel_launch(void* const* d_in, const int* in_sizes, int n_in,
                              void* d_out, int out_size) {
    const float* x     = (const float*)d_in[0];
    const void*  eidx  = d_in[1];
    const float* eattr = (const float*)d_in[2];
    const float* We1   = (const float*)d_in[3];
    const float* be1   = (const float*)d_in[4];
    const float* We2   = (const float*)d_in[5];
    const float* be2   = (const float*)d_in[6];
    const float* Wn1   = (const float*)d_in[7];
    const float* bn1   = (const float*)d_in[8];
    const float* Wn2   = (const float*)d_in[9];
    const float* bn2   = (const float*)d_in[10];
    float* out = (float*)d_out;

    const int N = in_sizes[0] / H;
    const int E = in_sizes[1] / 2;

    cudaFuncSetAttribute(gemm_kernel, cudaFuncAttributeMaxDynamicSharedMemorySize, DYN_GEMM);
    cudaFuncSetAttribute(edge_kernel, cudaFuncAttributeMaxDynamicSharedMemorySize, DYN_EDGE);
    cudaFuncSetAttribute(node_kernel, cudaFuncAttributeMaxDynamicSharedMemorySize, DYN_NODE);

    float* zerop; cudaGetSymbolAddress((void**)&zerop, g_zero);
    float* degp;  cudaGetSymbolAddress((void**)&degp,  g_deg);
    float* aggp;  cudaGetSymbolAddress((void**)&aggp,  g_agg);
    float* Pap;   cudaGetSymbolAddress((void**)&Pap,   g_Pa);
    float* Pbp;   cudaGetSymbolAddress((void**)&Pbp,   g_Pb);
    float* Rp;    cudaGetSymbolAddress((void**)&Rp,    g_R);
    float* Waimg; cudaGetSymbolAddress((void**)&Waimg, g_Wa);
    float* Wbimg; cudaGetSymbolAddress((void**)&Wbimg, g_Wb);
    float* We2i;  cudaGetSymbolAddress((void**)&We2i,  g_We2img);
    float* Wn1ti; cudaGetSymbolAddress((void**)&Wn1ti, g_Wn1t);

    // Launch order (ncu -s 5 -c 1 lands on edge_kernel):
    // 1:zero 2:detect 3:prep 4:gemm(Pa) 5:gemm(Pb) 6:edge 7:gemm(R) 8:gemm(agg) 9:node
    const int n4 = N * H / 4;
    zero_kernel<<<(n4 + 255) / 256, 256>>>(n4, (N + 3) / 4);
    detect_idx_kernel<<<1, 1>>>((const unsigned int*)eidx);
    prep_all_kernel<<<448, 256>>>(We1, We2, Wn1, Wn2);

    gemm_kernel<<<304, 256, DYN_GEMM>>>(x, Waimg, be1,   nullptr, Pap, N);   // Pa
    gemm_kernel<<<304, 256, DYN_GEMM>>>(x, Wbimg, zerop, nullptr, Pbp, N);   // Pb

    edge_kernel<<<304, 256, DYN_EDGE>>>(eattr, eidx, E);

    gemm_kernel<<<304, 256, DYN_GEMM>>>(x, Wn1ti, bn1, nullptr, Rp, N);      // R
    gemm_kernel<<<304, 256, DYN_GEMM>>>(aggp, We2i, be2, degp, aggp, N);     // agg (in-place)

    node_kernel<<<152, 256, DYN_NODE>>>(bn2, out, N);
}

// round 7
// speedup vs baseline: 10.8084x; 1.0839x over previous
#include <cuda_runtime.h>
#include <cstdint>

#define H     128
#define MAX_N 50000
#define MAX_E 800000
#define NPAD  50048

// ---------------------------------------------------------------------------
// Scratch (device globals: no allocations allowed)
// ---------------------------------------------------------------------------
__device__ float g_agg[NPAD * H];          // Hsum during edge phase, then agg (in-place)
__device__ float g_deg[NPAD];              // per-node in-degree (float)
__device__ float g_Pa[NPAD * H];           // x @ Wa + be1
__device__ float g_Pb[NPAD * H];           // x @ Wb
__device__ float g_R [NPAD * H];           // x @ Wn1_top + bn1
// tf32 weight images, n-major + granule swizzle for ldmatrix (4 chunks x 4096 floats)
__device__ float g_Wa[16384], g_Wb[16384], g_Wc[16384];
__device__ float g_We2img[16384];
__device__ float g_Wn1t[16384], g_Wn1b[16384], g_Wn2img[16384];
__device__ int   g_is64;

// ---------------------------------------------------------------------------
// helpers
// ---------------------------------------------------------------------------
__device__ __forceinline__ uint32_t smem_u32(const void* p) {
    uint32_t a;
    asm("{ .reg .u64 t; cvta.to.shared.u64 t, %1; cvt.u32.u64 %0, t; }" : "=r"(a) : "l"(p));
    return a;
}
__device__ __forceinline__ void cp16(uint32_t dst, const void* src, uint32_t sz) {
    asm volatile("cp.async.ca.shared.global [%0], [%1], 16, %2;"
                 :: "r"(dst), "l"(src), "r"(sz) : "memory");
}
#define CP_COMMIT() asm volatile("cp.async.commit_group;" ::: "memory")
#define CP_WAIT(n)  asm volatile("cp.async.wait_group %0;" :: "n"(n) : "memory")

__device__ __forceinline__ uint32_t cvt_tf32(float v) {
    uint32_t r; asm("cvt.rna.tf32.f32 %0, %1;" : "=r"(r) : "f"(v)); return r;
}
__device__ __forceinline__ void mma8(float* c, const uint32_t* a, const uint32_t* b) {
    asm volatile("mma.sync.aligned.m16n8k8.row.col.f32.tf32.tf32.f32 "
        "{%0,%1,%2,%3},{%4,%5,%6,%7},{%8,%9},{%0,%1,%2,%3};"
        : "+f"(c[0]), "+f"(c[1]), "+f"(c[2]), "+f"(c[3])
        : "r"(a[0]), "r"(a[1]), "r"(a[2]), "r"(a[3]), "r"(b[0]), "r"(b[1]));
}
__device__ __forceinline__ void ldmx4(uint32_t* r, uint32_t addr) {
    asm volatile("ldmatrix.sync.aligned.m8n8.x4.shared.b16 {%0,%1,%2,%3}, [%4];"
        : "=r"(r[0]), "=r"(r[1]), "=r"(r[2]), "=r"(r[3]) : "r"(addr));
}
__device__ __forceinline__ void red4(float* p, float a, float b, float c, float d) {
    asm volatile("red.global.add.v4.f32 [%0], {%1, %2, %3, %4};"
                 :: "l"(p), "f"(a), "f"(b), "f"(c), "f"(d) : "memory");
}
__device__ __forceinline__ void red1(float* p, float a) {
    asm volatile("red.global.add.f32 [%0], %1;" :: "l"(p), "f"(a) : "memory");
}

// ---------------------------------------------------------------------------
// setup: zero agg/deg + build all 7 weight images
// n-major ldmatrix image: value W[row_off + c*32 + kk][n] stored at byte
// c*16384 + n*128 + ((kk>>2)^(n&7))*16 + (kk&3)*4, tf32(rna) pre-rounded.
// ---------------------------------------------------------------------------
__global__ void setup_kernel(const float* __restrict__ We1, const float* __restrict__ We2,
                             const float* __restrict__ Wn1, const float* __restrict__ Wn2,
                             int n4, int nd4) {
    int i = blockIdx.x * blockDim.x + threadIdx.x;
    if (i < n4) ((float4*)g_agg)[i] = make_float4(0.f, 0.f, 0.f, 0.f);
    if (i < nd4) ((float4*)g_deg)[i] = make_float4(0.f, 0.f, 0.f, 0.f);
    if (blockIdx.x < 448) {
        int which = blockIdx.x >> 6;
        int idx = ((blockIdx.x & 63) << 8) + threadIdx.x;   // 0..16383
        const float* W; int row_off; float* img;
        switch (which) {
            case 0: W = We1; row_off =   0; img = g_Wa;     break;
            case 1: W = We1; row_off = 128; img = g_Wb;     break;
            case 2: W = We1; row_off = 256; img = g_Wc;     break;
            case 3: W = We2; row_off =   0; img = g_We2img; break;
            case 4: W = Wn1; row_off =   0; img = g_Wn1t;   break;
            case 5: W = Wn1; row_off = 128; img = g_Wn1b;   break;
            default: W = Wn2; row_off =  0; img = g_Wn2img; break;
        }
        int c = idx >> 12, rem = idx & 4095, kk = rem >> 7, n = rem & 127;
        float v = W[(size_t)(row_off + c * 32 + kk) * H + n];
        ((uint32_t*)img)[c * 4096 + n * 32 + (((kk >> 2) ^ (n & 7)) << 2) + (kk & 3)] = cvt_tf32(v);
    }
}
__global__ void detect_idx_kernel(const unsigned int* __restrict__ e) {
    g_is64 = (e[1] == 0u && e[3] == 0u && e[5] == 0u && e[7] == 0u) ? 1 : 0;
}

// ===========================================================================
// Tile machinery: 128x128 tile, 8 warps (4M x 2N), tf32 mma.sync + ldmatrix
// A SMEM layout: row r = 128B, k-granule q stored at (q ^ (r&7))*16
// B image layout: n-major, see setup_kernel
// ===========================================================================
struct TileCtx {
    int lane, g, t, wM, wN, ar, halfA, l7;
    uint32_t khA, khB, aRow0, aRow1, bRow0, bRow1, bRow2, bRow3;
    __device__ __forceinline__ void init(int tid) {
        lane = tid & 31;
        int warp = tid >> 5;
        g = lane >> 2; t = lane & 3;
        wM = warp & 3; wN = warp >> 2;
        ar = tid >> 1; halfA = tid & 1;
        l7 = lane & 7;
        khA = (uint32_t)(lane >> 4);
        khB = (uint32_t)((lane >> 3) & 1);
        aRow0 = (uint32_t)((wM * 32 + ((lane >> 3) & 1) * 8 + l7) * 128);
        aRow1 = aRow0 + 16 * 128;
        uint32_t jo = (uint32_t)(lane >> 4);
        bRow0 = (uint32_t)((wN * 64 + (0 + jo) * 8 + l7) * 128);
        bRow1 = (uint32_t)((wN * 64 + (2 + jo) * 8 + l7) * 128);
        bRow2 = (uint32_t)((wN * 64 + (4 + jo) * 8 + l7) * 128);
        bRow3 = (uint32_t)((wN * 64 + (6 + jo) * 8 + l7) * 128);
    }
};

template<bool DOCVT>
__device__ __forceinline__ void kstep(const TileCtx& cx, float acc[2][8][4],
                                      uint32_t Ab, uint32_t Bb, int ks) {
    uint32_t gA = (uint32_t)(((2 * ks + cx.khA) ^ cx.l7) << 4);
    uint32_t gB = (uint32_t)(((2 * ks + cx.khB) ^ cx.l7) << 4);
    uint32_t a0[4], a1[4];
    ldmx4(a0, Ab + cx.aRow0 + gA);
    ldmx4(a1, Ab + cx.aRow1 + gA);
    if (DOCVT) {
        #pragma unroll
        for (int i = 0; i < 4; i++) {
            a0[i] = cvt_tf32(__uint_as_float(a0[i]));
            a1[i] = cvt_tf32(__uint_as_float(a1[i]));
        }
    }
    uint32_t bf[16];
    ldmx4(bf + 0,  Bb + cx.bRow0 + gB);
    ldmx4(bf + 4,  Bb + cx.bRow1 + gB);
    ldmx4(bf + 8,  Bb + cx.bRow2 + gB);
    ldmx4(bf + 12, Bb + cx.bRow3 + gB);
    #pragma unroll
    for (int jn = 0; jn < 8; jn++) {
        mma8(acc[0][jn], a0, bf + 2 * jn);
        mma8(acc[1][jn], a1, bf + 2 * jn);
    }
}

// ---------------------------------------------------------------------------
// Fused precompute: one pass over x, three weight images:
// Pa = x@Wa + be1, Pb = x@Wb, R = x@Wn1t + bn1
// smem floats: A full tile 16384 | B dbuf 2x4096 = 24576 (96KB) -> 2 CTA/SM
// ---------------------------------------------------------------------------
__global__ void __launch_bounds__(256, 2)
precompute_kernel(const float* __restrict__ x, const float* __restrict__ be1,
                  const float* __restrict__ bn1, int M)
{
    extern __shared__ __align__(16) float sm[];
    __shared__ float sB1[128], sBn[128];
    const int tid = threadIdx.x;
    TileCtx cx; cx.init(tid);
    const uint32_t aBufU = smem_u32(sm);
    const uint32_t bBufU = smem_u32(sm + 16384);
    if (tid < 128) { sB1[tid] = be1[tid]; sBn[tid] = bn1[tid]; }

    const int T = (M + 127) >> 7;
    for (int tile = blockIdx.x; tile < T; tile += gridDim.x) {
        const int mbase = tile << 7;
        __syncthreads();

        auto stageA = [&](int c) {
            bool valid = (mbase + cx.ar) < M;
            const float* srcA = x + (size_t)(valid ? (mbase + cx.ar) : 0) * H
                              + (c << 5) + cx.halfA * 16;
            uint32_t dstA = aBufU + (uint32_t)(c * 16384 + cx.ar * 128);
            uint32_t sz = valid ? 16u : 0u;
            #pragma unroll
            for (int i = 0; i < 4; i++) {
                int q = cx.halfA * 4 + i, qs = q ^ (cx.ar & 7);
                cp16(dstA + qs * 16, srcA + i * 4, sz);
            }
        };
        auto stageB = [&](int s) {
            const float* img = ((s >> 2) == 0) ? g_Wa : ((s >> 2) == 1) ? g_Wb : g_Wn1t;
            const float4* srcB = (const float4*)(img + (s & 3) * 4096) + tid;
            uint32_t dstB = bBufU + (uint32_t)((s & 1) * 16384) + (uint32_t)tid * 16;
            #pragma unroll
            for (int i = 0; i < 4; i++) cp16(dstB + i * 4096, srcB + i * 256, 16);
        };

        float acc[2][8][4];
        #pragma unroll
        for (int mt = 0; mt < 2; mt++)
            #pragma unroll
            for (int jn = 0; jn < 8; jn++)
                #pragma unroll
                for (int i = 0; i < 4; i++) acc[mt][jn][i] = 0.f;

        stageA(0); stageB(0); CP_COMMIT();
        stageA(1); stageB(1); CP_COMMIT();

        for (int s = 0; s < 12; s++) {
            if (s < 11) { CP_WAIT(1); } else { CP_WAIT(0); }
            __syncthreads();
            uint32_t Ab = aBufU + (uint32_t)((s & 3) * 16384);
            uint32_t Bb = bBufU + (uint32_t)((s & 1) * 16384);
            #pragma unroll
            for (int ks = 0; ks < 4; ks++) kstep<true>(cx, acc, Ab, Bb, ks);
            __syncthreads();
            int ns = s + 2;
            if (ns < 12) {
                if (ns < 4) stageA(ns);
                stageB(ns);
                CP_COMMIT();
            }
            if ((s & 3) == 3) {   // end of a pass: epilogue + reset acc
                int pass = s >> 2;
                float* outp = (pass == 0) ? g_Pa : (pass == 1) ? g_Pb : g_R;
                #pragma unroll
                for (int mt = 0; mt < 2; mt++) {
                    const int r0r = cx.wM * 32 + cx.g + mt * 16, r8r = r0r + 8;
                    #pragma unroll
                    for (int jn = 0; jn < 8; jn++) {
                        int col0 = cx.wN * 64 + jn * 8 + 2 * cx.t;
                        float b0 = 0.f, b1 = 0.f;
                        if (pass == 0) { b0 = sB1[col0]; b1 = sB1[col0 + 1]; }
                        if (pass == 2) { b0 = sBn[col0]; b1 = sBn[col0 + 1]; }
                        if (mbase + r0r < M)
                            *(float2*)(outp + (size_t)(mbase + r0r) * H + col0) =
                                make_float2(acc[mt][jn][0] + b0, acc[mt][jn][1] + b1);
                        if (mbase + r8r < M)
                            *(float2*)(outp + (size_t)(mbase + r8r) * H + col0) =
                                make_float2(acc[mt][jn][2] + b0, acc[mt][jn][3] + b1);
                        acc[mt][jn][0] = acc[mt][jn][1] = 0.f;
                        acc[mt][jn][2] = acc[mt][jn][3] = 0.f;
                    }
                }
            }
        }
    }
}

// ---------------------------------------------------------------------------
// Generic GEMM (used for agg = Hsum@We2 + deg*be2, in-place)
// ---------------------------------------------------------------------------
__global__ void __launch_bounds__(256, 2)
gemm_kernel(const float* __restrict__ srcA, const float* __restrict__ Wimg,
            const float* __restrict__ bias, const float* __restrict__ degv,
            float* __restrict__ outp, int M)
{
    extern __shared__ __align__(16) float sm[];
    __shared__ float sB[128];
    const int tid = threadIdx.x;
    TileCtx cx; cx.init(tid);
    const uint32_t aBufU = smem_u32(sm);
    const uint32_t bBufU = smem_u32(sm + 8192);
    if (tid < 128) sB[tid] = bias[tid];

    const int T = (M + 127) >> 7;
    for (int tile = blockIdx.x; tile < T; tile += gridDim.x) {
        const int mbase = tile << 7;
        __syncthreads();

        auto stage = [&](int c) {
            bool valid = (mbase + cx.ar) < M;
            const float* srcAr = srcA + (size_t)(valid ? (mbase + cx.ar) : 0) * H
                               + (c << 5) + cx.halfA * 16;
            uint32_t dstA = aBufU + (uint32_t)((c & 1) * 16384 + cx.ar * 128);
            uint32_t sz = valid ? 16u : 0u;
            #pragma unroll
            for (int i = 0; i < 4; i++) {
                int q = cx.halfA * 4 + i, qs = q ^ (cx.ar & 7);
                cp16(dstA + qs * 16, srcAr + i * 4, sz);
            }
            const float4* srcB = (const float4*)(Wimg + c * 4096) + tid;
            uint32_t dstB = bBufU + (uint32_t)((c & 1) * 16384) + (uint32_t)tid * 16;
            #pragma unroll
            for (int i = 0; i < 4; i++) cp16(dstB + i * 4096, srcB + i * 256, 16);
            CP_COMMIT();
        };

        float acc[2][8][4];
        #pragma unroll
        for (int mt = 0; mt < 2; mt++)
            #pragma unroll
            for (int jn = 0; jn < 8; jn++)
                #pragma unroll
                for (int i = 0; i < 4; i++) acc[mt][jn][i] = 0.f;

        stage(0); stage(1);
        #pragma unroll
        for (int c = 0; c < 4; c++) {
            if (c < 3) { CP_WAIT(1); } else { CP_WAIT(0); }
            __syncthreads();
            uint32_t Ab = aBufU + (uint32_t)((c & 1) * 16384);
            uint32_t Bb = bBufU + (uint32_t)((c & 1) * 16384);
            #pragma unroll
            for (int ks = 0; ks < 4; ks++) kstep<true>(cx, acc, Ab, Bb, ks);
            __syncthreads();
            if (c + 2 < 4) stage(c + 2);
        }

        #pragma unroll
        for (int mt = 0; mt < 2; mt++) {
            const int r0r = cx.wM * 32 + cx.g + mt * 16, r8r = r0r + 8;
            float s0 = 1.f, s8 = 1.f;
            if (degv) {
                s0 = (mbase + r0r < M) ? degv[mbase + r0r] : 0.f;
                s8 = (mbase + r8r < M) ? degv[mbase + r8r] : 0.f;
            }
            #pragma unroll
            for (int jn = 0; jn < 8; jn++) {
                int col0 = cx.wN * 64 + jn * 8 + 2 * cx.t;
                float b0 = sB[col0], b1 = sB[col0 + 1];
                if (mbase + r0r < M)
                    *(float2*)(outp + (size_t)(mbase + r0r) * H + col0) =
                        make_float2(acc[mt][jn][0] + s0 * b0, acc[mt][jn][1] + s0 * b1);
                if (mbase + r8r < M)
                    *(float2*)(outp + (size_t)(mbase + r8r) * H + col0) =
                        make_float2(acc[mt][jn][2] + s8 * b0, acc[mt][jn][3] + s8 * b1);
            }
        }
    }
}

// ---------------------------------------------------------------------------
// Edge kernel: Q = eattr@Wc (Wc persistent in SMEM);
// hid = relu(Q + Pa[row] + Pb[col]); red.v4 (paired via shfl) into g_agg[col];
// deg[col] += 1.
// smem floats: A dbuf 8192 | sW1 16384 = 24576 (96KB) -> 2 CTAs/SM
// ---------------------------------------------------------------------------
__global__ void __launch_bounds__(256, 2)
edge_kernel(const float* __restrict__ eattr, const void* __restrict__ eidx, int M)
{
    extern __shared__ __align__(16) float sm[];
    float* const sW1 = sm + 8192;
    __shared__ int sRow[128], sCol[128];

    const int tid = threadIdx.x;
    TileCtx cx; cx.init(tid);
    const uint32_t aBufU = smem_u32(sm);
    const uint32_t w1U   = smem_u32(sW1);

    { // persistent Wc image
        const float4* s1 = (const float4*)g_Wc;
        float4* d1 = (float4*)sW1;
        #pragma unroll
        for (int i = 0; i < 16; i++) d1[tid + i * 256] = s1[tid + i * 256];
    }
    const int is64v = g_is64;
    __syncthreads();

    const int ntiles = (M + 127) >> 7;
    for (int tile = blockIdx.x; tile < ntiles; tile += gridDim.x) {
        const int mbase = tile << 7;
        __syncthreads();                 // prev-tile epilogue readers of sCol done
        if (tid < 128) {
            int e = mbase + tid; int rI = 0, cI = 0;
            if (e < M) {
                if (is64v) {
                    const long long* p = (const long long*)eidx;
                    rI = (int)p[e]; cI = (int)p[(long long)M + e];
                } else {
                    const int* p = (const int*)eidx;
                    rI = p[e]; cI = p[M + e];
                }
            }
            sRow[tid] = rI; sCol[tid] = cI;
        }
        __syncthreads();

        auto stage = [&](int c) {
            bool valid = (mbase + cx.ar) < M;
            const float* srcA = eattr + (size_t)(valid ? (mbase + cx.ar) : 0) * H
                              + (c << 5) + cx.halfA * 16;
            uint32_t dstA = aBufU + (uint32_t)((c & 1) * 16384 + cx.ar * 128);
            uint32_t sz = valid ? 16u : 0u;
            #pragma unroll
            for (int i = 0; i < 4; i++) {
                int q = cx.halfA * 4 + i, qs = q ^ (cx.ar & 7);
                cp16(dstA + qs * 16, srcA + i * 4, sz);
            }
            CP_COMMIT();
        };

        float acc[2][8][4];
        #pragma unroll
        for (int mt = 0; mt < 2; mt++)
            #pragma unroll
            for (int jn = 0; jn < 8; jn++)
                #pragma unroll
                for (int i = 0; i < 4; i++) acc[mt][jn][i] = 0.f;

        stage(0); stage(1);
        #pragma unroll
        for (int c = 0; c < 4; c++) {
            if (c < 3) { CP_WAIT(1); } else { CP_WAIT(0); }
            __syncthreads();
            uint32_t Ab = aBufU + (uint32_t)((c & 1) * 16384);
            uint32_t Bb = w1U + (uint32_t)(c * 16384);
            #pragma unroll
            for (int ks = 0; ks < 4; ks++) kstep<true>(cx, acc, Ab, Bb, ks);
            __syncthreads();
            if (c + 2 < 4) stage(c + 2);
        }

        // ---- epilogue: hid = relu(acc + Pa[row] + Pb[col]); paired red.v4 ----
        #pragma unroll
        for (int mt = 0; mt < 2; mt++) {
            const int r0r = cx.wM * 32 + cx.g + mt * 16, r8r = r0r + 8;
            const bool v0r = (mbase + r0r) < M, v8r = (mbase + r8r) < M;
            const int ia0 = sRow[r0r], ic0 = sCol[r0r];
            const int ia8 = sRow[r8r], ic8 = sCol[r8r];
            const float* pa0 = g_Pa + (size_t)ia0 * H;
            const float* pa8 = g_Pa + (size_t)ia8 * H;
            const float* pb0 = g_Pb + (size_t)ic0 * H;
            const float* pb8 = g_Pb + (size_t)ic8 * H;
            float* h0 = g_agg + (size_t)ic0 * H;
            float* h8 = g_agg + (size_t)ic8 * H;
            if (cx.wN == 0 && cx.t == 0) {
                if (v0r) red1(g_deg + ic0, 1.f);
                if (v8r) red1(g_deg + ic8, 1.f);
            }
            #pragma unroll
            for (int jn = 0; jn < 8; jn++) {
                int col0 = cx.wN * 64 + jn * 8 + 2 * cx.t;
                float2 a0 = *(const float2*)(pa0 + col0);
                float2 b0 = *(const float2*)(pb0 + col0);
                float2 a8 = *(const float2*)(pa8 + col0);
                float2 b8 = *(const float2*)(pb8 + col0);
                float v0 = fmaxf(acc[mt][jn][0] + a0.x + b0.x, 0.f);
                float v1 = fmaxf(acc[mt][jn][1] + a0.y + b0.y, 0.f);
                float v2 = fmaxf(acc[mt][jn][2] + a8.x + b8.x, 0.f);
                float v3 = fmaxf(acc[mt][jn][3] + a8.y + b8.y, 0.f);
                // pair adjacent t-threads: even t writes 4 contiguous cols
                float q0 = __shfl_xor_sync(0xffffffffu, v0, 1);
                float q1 = __shfl_xor_sync(0xffffffffu, v1, 1);
                float q2 = __shfl_xor_sync(0xffffffffu, v2, 1);
                float q3 = __shfl_xor_sync(0xffffffffu, v3, 1);
                if (!(cx.t & 1)) {
                    if (v0r) red4(h0 + col0, v0, v1, q0, q1);
                    if (v8r) red4(h8 + col0, v2, v3, q2, q3);
                }
            }
        }
    }
}

// ---------------------------------------------------------------------------
// Node kernel: Q = agg@Wn1b; hid = relu(Q + R[m]); out = hid@Wn2 + bn2
// smem floats: A dbuf 8192 | sW1 16384 | sW2 16384 | sHid 16384 = 57344 (224KB)
// ---------------------------------------------------------------------------
__global__ void __launch_bounds__(256, 1)
node_kernel(const float* __restrict__ b2v, float* __restrict__ outp, int M)
{
    extern __shared__ __align__(16) float sm[];
    float* const sW1  = sm + 8192;
    float* const sW2  = sm + 24576;
    float* const sHid = sm + 40960;
    __shared__ float sB2[128];

    const int tid = threadIdx.x;
    TileCtx cx; cx.init(tid);
    const uint32_t aBufU = smem_u32(sm);
    const uint32_t w1U   = smem_u32(sW1);
    const uint32_t w2U   = smem_u32(sW2);
    const uint32_t hidU  = smem_u32(sHid);

    {
        const float4* s1 = (const float4*)g_Wn1b;
        const float4* s2 = (const float4*)g_Wn2img;
        float4* d1 = (float4*)sW1; float4* d2 = (float4*)sW2;
        #pragma unroll
        for (int i = 0; i < 16; i++) { d1[tid + i * 256] = s1[tid + i * 256];
                                       d2[tid + i * 256] = s2[tid + i * 256]; }
    }
    if (tid < 128) sB2[tid] = b2v[tid];
    __syncthreads();

    const int ntiles = (M + 127) >> 7;
    for (int tile = blockIdx.x; tile < ntiles; tile += gridDim.x) {
        const int mbase = tile << 7;
        __syncthreads();

        auto stage = [&](int c) {
            bool valid = (mbase + cx.ar) < M;
            const float* srcA = g_agg + (size_t)(valid ? (mbase + cx.ar) : 0) * H
                              + (c << 5) + cx.halfA * 16;
            uint32_t dstA = aBufU + (uint32_t)((c & 1) * 16384 + cx.ar * 128);
            uint32_t sz = valid ? 16u : 0u;
            #pragma unroll
            for (int i = 0; i < 4; i++) {
                int q = cx.halfA * 4 + i, qs = q ^ (cx.ar & 7);
                cp16(dstA + qs * 16, srcA + i * 4, sz);
            }
            CP_COMMIT();
        };

        float acc[2][8][4];
        #pragma unroll
        for (int mt = 0; mt < 2; mt++)
            #pragma unroll
            for (int jn = 0; jn < 8; jn++)
                #pragma unroll
                for (int i = 0; i < 4; i++) acc[mt][jn][i] = 0.f;

        stage(0); stage(1);
        #pragma unroll
        for (int c = 0; c < 4; c++) {
            if (c < 3) { CP_WAIT(1); } else { CP_WAIT(0); }
            __syncthreads();
            uint32_t Ab = aBufU + (uint32_t)((c & 1) * 16384);
            uint32_t Bb = w1U + (uint32_t)(c * 16384);
            #pragma unroll
            for (int ks = 0; ks < 4; ks++) kstep<true>(cx, acc, Ab, Bb, ks);
            __syncthreads();
            if (c + 2 < 4) stage(c + 2);
        }

        // hid = relu(acc + R[m]) -> sHid (tf32, A layout)
        const int axor = cx.g << 2;
        #pragma unroll
        for (int mt = 0; mt < 2; mt++) {
            const int r0r = cx.wM * 32 + cx.g + mt * 16, r8r = r0r + 8;
            const int ia0 = min(mbase + r0r, M - 1);
            const int ia8 = min(mbase + r8r, M - 1);
            #pragma unroll
            for (int jn = 0; jn < 8; jn++) {
                int col0 = cx.wN * 64 + jn * 8 + 2 * cx.t;
                float2 ra = *(const float2*)(g_R + (size_t)ia0 * H + col0);
                float2 rb = *(const float2*)(g_R + (size_t)ia8 * H + col0);
                uint32_t u0 = cvt_tf32(fmaxf(acc[mt][jn][0] + ra.x, 0.f));
                uint32_t u1 = cvt_tf32(fmaxf(acc[mt][jn][1] + ra.y, 0.f));
                uint32_t u2 = cvt_tf32(fmaxf(acc[mt][jn][2] + rb.x, 0.f));
                uint32_t u3 = cvt_tf32(fmaxf(acc[mt][jn][3] + rb.y, 0.f));
                int slab = col0 >> 5, kk = col0 & 31;
                uint32_t* dst = (uint32_t*)(sHid + slab * 4096);
                *(uint2*)(dst + r0r * 32 + (kk ^ axor)) = make_uint2(u0, u1);
                *(uint2*)(dst + r8r * 32 + (kk ^ axor)) = make_uint2(u2, u3);
                acc[mt][jn][0] = acc[mt][jn][1] = acc[mt][jn][2] = acc[mt][jn][3] = 0.f;
            }
        }
        __syncthreads();

        #pragma unroll
        for (int ks16 = 0; ks16 < 16; ks16++)
            kstep<false>(cx, acc,
                         hidU + (uint32_t)((ks16 >> 2) * 16384),
                         w2U  + (uint32_t)((ks16 >> 2) * 16384), ks16 & 3);

        #pragma unroll
        for (int mt = 0; mt < 2; mt++) {
            const int r0r = cx.wM * 32 + cx.g + mt * 16, r8r = r0r + 8;
            #pragma unroll
            for (int jn = 0; jn < 8; jn++) {
                int col0 = cx.wN * 64 + jn * 8 + 2 * cx.t;
                float b0 = sB2[col0], b1 = sB2[col0 + 1];
                if (mbase + r0r < M)
                    *(float2*)(outp + (size_t)(mbase + r0r) * H + col0) =
                        make_float2(acc[mt][jn][0] + b0, acc[mt][jn][1] + b1);
                if (mbase + r8r < M)
                    *(float2*)(outp + (size_t)(mbase + r8r) * H + col0) =
                        make_float2(acc[mt][jn][2] + b0, acc[mt][jn][3] + b1);
            }
        }
    }
}

// ---------------------------------------------------------------------------
#define DYN_GEMM (16384 * 4)   //  64KB
#define DYN_PRE  (24576 * 4)   //  96KB
#define DYN_EDGE (24576 * 4)   //  96KB
#define DYN_NODE (57344 * 4)   // 224KB

extern "C" void kernel_launch(void* const* d_in, const int* in_sizes, int n_in,
                              void* d_out, int out_size) {
    const float* x     = (const float*)d_in[0];
    const void*  eidx  = d_in[1];
    const float* eattr = (const float*)d_in[2];
    const float* We1   = (const float*)d_in[3];
    const float* be1   = (const float*)d_in[4];
    const float* We2   = (const float*)d_in[5];
    const float* be2   = (const float*)d_in[6];
    const float* Wn1   = (const float*)d_in[7];
    const float* bn1   = (const float*)d_in[8];
    const float* Wn2   = (const float*)d_in[9];
    const float* bn2   = (const float*)d_in[10];
    float* out = (float*)d_out;

    const int N = in_sizes[0] / H;
    const int E = in_sizes[1] / 2;

    cudaFuncSetAttribute(gemm_kernel,       cudaFuncAttributeMaxDynamicSharedMemorySize, DYN_GEMM);
    cudaFuncSetAttribute(precompute_kernel, cudaFuncAttributeMaxDynamicSharedMemorySize, DYN_PRE);
    cudaFuncSetAttribute(edge_kernel,       cudaFuncAttributeMaxDynamicSharedMemorySize, DYN_EDGE);
    cudaFuncSetAttribute(node_kernel,       cudaFuncAttributeMaxDynamicSharedMemorySize, DYN_NODE);

    float* degp;  cudaGetSymbolAddress((void**)&degp,  g_deg);
    float* aggp;  cudaGetSymbolAddress((void**)&aggp,  g_agg);
    float* We2i;  cudaGetSymbolAddress((void**)&We2i,  g_We2img);

    // Launch order (ncu captures the 4th launch -> edge_kernel):
    // 1:setup 2:precompute 3:detect 4:edge 5:gemm(agg) 6:node
    const int n4 = N * H / 4;
    setup_kernel<<<(n4 + 255) / 256, 256>>>(We1, We2, Wn1, Wn2, n4, (N + 3) / 4);
    precompute_kernel<<<304, 256, DYN_PRE>>>(x, be1, bn1, N);
    detect_idx_kernel<<<1, 1>>>((const unsigned int*)eidx);

    edge_kernel<<<304, 256, DYN_EDGE>>>(eattr, eidx, E);

    gemm_kernel<<<304, 256, DYN_GEMM>>>(aggp, We2i, be2, degp, aggp, N);  // agg in-place
    node_kernel<<<152, 256, DYN_NODE>>>(bn2, out, N);
}